// round 1
// baseline (speedup 1.0000x reference)
#include <cuda_runtime.h>
#include <math.h>

#define NN 50000
#define NE 800000
#define NT 850000          // NE + NN self loops
#define HID 128
#define EPSV 1e-5f

// ---------------- scratch (device globals; no allocations) ----------------
__device__ float g_x [NN*HID];
__device__ float g_xl[NN*HID];
__device__ float g_xr[NN*HID];
__device__ float g_h [NN*HID];
__device__ float g_hn[NN*HID];
__device__ int   g_cnt[NN];
__device__ int   g_rowptr[NN+1];
__device__ int   g_fill[NN];
__device__ int   g_csrc[NT];
__device__ float g_stats[256];     // [0:128) sum, [128:256) sumsq
__device__ float g_scale[HID];
__device__ float g_shift[HID];

// ---------------- setup kernels ----------------
__global__ void k_copy_x(const float* __restrict__ x){
  int i = blockIdx.x*blockDim.x + threadIdx.x;
  if(i < NN*HID/4) ((float4*)g_x)[i] = ((const float4*)x)[i];
}

__global__ void k_zero_cnt(){
  int i = blockIdx.x*blockDim.x + threadIdx.x;
  if(i < NN) g_cnt[i] = 0;
}

__global__ void k_count(const int* __restrict__ ei){
  int i = blockIdx.x*blockDim.x + threadIdx.x;
  if(i >= NT) return;
  int d = (i < NE) ? ei[NE + i] : (i - NE);
  atomicAdd(&g_cnt[d], 1);
}

__global__ void k_scan(){        // 1 block, 1024 threads
  __shared__ int sh[1024];
  int t = threadIdx.x;
  const int CH = 49;             // 1024*49 = 50176 >= NN
  int b0 = t*CH;
  int e0 = min(b0 + CH, NN);
  int s = 0;
  for(int i = b0; i < e0; i++) s += g_cnt[i];
  sh[t] = s; __syncthreads();
  for(int off = 1; off < 1024; off <<= 1){
    int v = (t >= off) ? sh[t-off] : 0;
    __syncthreads();
    sh[t] += v;
    __syncthreads();
  }
  int run = sh[t] - s;           // exclusive prefix
  for(int i = b0; i < e0; i++){
    g_rowptr[i] = run; g_fill[i] = run;
    run += g_cnt[i];
  }
  if(t == 1023) g_rowptr[NN] = sh[1023];
}

__global__ void k_scatter(const int* __restrict__ ei){
  int i = blockIdx.x*blockDim.x + threadIdx.x;
  if(i >= NT) return;
  int s, d;
  if(i < NE){ s = ei[i]; d = ei[NE + i]; }
  else      { s = d = i - NE; }
  int pos = atomicAdd(&g_fill[d], 1);
  g_csrc[pos] = s;
}

// ---------------- SGEMM: C[M,128] = A[M,128] @ W[128,128] (+bias)(+add) ----------------
__device__ __forceinline__ void gemm_body(
  const float* __restrict__ A, const float* __restrict__ W,
  const float* __restrict__ bias, const float* __restrict__ add,
  float* __restrict__ C)
{
  __shared__ float As[128][33];
  __shared__ float Bs[32][128];
  const int t  = threadIdx.x;          // 256
  const int bm = blockIdx.x * 128;
  const int tx = t & 15, ty = t >> 4;
  float acc[8][8];
  #pragma unroll
  for(int i = 0; i < 8; i++)
    #pragma unroll
    for(int j = 0; j < 8; j++) acc[i][j] = 0.f;

  const int ar = t >> 3, ac = (t & 7) * 4;
  const int br = t >> 5, bc = (t & 31) * 4;
  for(int kt = 0; kt < 128; kt += 32){
    #pragma unroll
    for(int i = 0; i < 4; i++){
      int r = ar + i*32;
      int grow = bm + r;
      float4 v = make_float4(0.f,0.f,0.f,0.f);
      if(grow < NN) v = *(const float4*)(A + grow*128 + kt + ac);
      As[r][ac] = v.x; As[r][ac+1] = v.y; As[r][ac+2] = v.z; As[r][ac+3] = v.w;
    }
    #pragma unroll
    for(int i = 0; i < 4; i++){
      int r = br + i*8;
      *(float4*)(&Bs[r][bc]) = *(const float4*)(W + (kt + r)*128 + bc);
    }
    __syncthreads();
    #pragma unroll
    for(int kk = 0; kk < 32; kk++){
      float a[8], bb[8];
      #pragma unroll
      for(int i = 0; i < 8; i++) a[i]  = As[ty*8 + i][kk];
      #pragma unroll
      for(int j = 0; j < 8; j++) bb[j] = Bs[kk][tx*8 + j];
      #pragma unroll
      for(int i = 0; i < 8; i++)
        #pragma unroll
        for(int j = 0; j < 8; j++) acc[i][j] = fmaf(a[i], bb[j], acc[i][j]);
    }
    __syncthreads();
  }
  #pragma unroll
  for(int i = 0; i < 8; i++){
    int grow = bm + ty*8 + i;
    if(grow >= NN) continue;
    #pragma unroll
    for(int j = 0; j < 8; j += 4){
      int col = tx*8 + j;
      float4 r;
      r.x = acc[i][j]; r.y = acc[i][j+1]; r.z = acc[i][j+2]; r.w = acc[i][j+3];
      if(bias){
        r.x += bias[col]; r.y += bias[col+1]; r.z += bias[col+2]; r.w += bias[col+3];
      }
      if(add){
        float4 av = *(const float4*)(add + grow*128 + col);
        r.x += av.x; r.y += av.y; r.z += av.z; r.w += av.w;
      }
      *(float4*)(C + grow*128 + col) = r;
    }
  }
}

__global__ void k_gemm_xl(const float* __restrict__ W){ gemm_body(g_x,  W, nullptr, nullptr, g_xl); }
__global__ void k_gemm_xr(const float* __restrict__ W){ gemm_body(g_x,  W, nullptr, nullptr, g_xr); }
__global__ void k_gemm_skip(const float* __restrict__ W, const float* __restrict__ b){
  gemm_body(g_hn, W, b, g_x, g_x);
}

// ---------------- GATv2 attention + online-softmax aggregation ----------------
__device__ __forceinline__ float lrelu(float v){ return v > 0.f ? v : 0.2f*v; }

// one warp per node; lane L covers flat channel indices [4L, 4L+4) = head L/8, dims (L%8)*4..+3
__global__ void k_gat(const float* __restrict__ att, const float* __restrict__ convb){
  int warp = (blockIdx.x*blockDim.x + threadIdx.x) >> 5;
  if(warp >= NN) return;
  int lane = threadIdx.x & 31;
  int c4 = lane * 4;
  const float4 xr4 = *(const float4*)(g_xr + warp*128 + c4);
  const float4 at4 = *(const float4*)(att + c4);
  int pb = g_rowptr[warp], pe = g_rowptr[warp+1];

  float m = -3.4e38f;       // running max (per 8-lane head group; uniform in group)
  float ds = 0.f;           // running sum of exp
  float a0 = 0.f, a1 = 0.f, a2 = 0.f, a3 = 0.f;

  for(int p = pb; p < pe; p++){
    int s = g_csrc[p];
    float4 v = *(const float4*)(g_xl + s*128 + c4);
    float t = lrelu(v.x + xr4.x)*at4.x + lrelu(v.y + xr4.y)*at4.y
            + lrelu(v.z + xr4.z)*at4.z + lrelu(v.w + xr4.w)*at4.w;
    t += __shfl_xor_sync(0xffffffffu, t, 4);
    t += __shfl_xor_sync(0xffffffffu, t, 2);
    t += __shfl_xor_sync(0xffffffffu, t, 1);
    if(t <= m){
      float a = __expf(t - m);
      ds += a;
      a0 = fmaf(a, v.x, a0); a1 = fmaf(a, v.y, a1);
      a2 = fmaf(a, v.z, a2); a3 = fmaf(a, v.w, a3);
    } else {
      float f = __expf(m - t);        // rescale old state; new term has weight 1
      ds = fmaf(ds, f, 1.f);
      a0 = fmaf(a0, f, v.x); a1 = fmaf(a1, f, v.y);
      a2 = fmaf(a2, f, v.z); a3 = fmaf(a3, f, v.w);
      m = t;
    }
  }
  float inv = 1.f / ds;
  const float4 bb = *(const float4*)(convb + c4);
  float4 o;
  o.x = fmaf(a0, inv, bb.x); o.y = fmaf(a1, inv, bb.y);
  o.z = fmaf(a2, inv, bb.z); o.w = fmaf(a3, inv, bb.w);
  *(float4*)(g_h + warp*128 + c4) = o;
}

// ---------------- GraphNorm ----------------
__global__ void k_zero_stats(){
  int i = threadIdx.x;
  if(i < 256) g_stats[i] = 0.f;
}

__global__ void k_colsum(){
  __shared__ float ssum[256], ssq[256];
  int t = threadIdx.x; int c = t & 127; int half = t >> 7;
  float s = 0.f, q = 0.f;
  for(int r = blockIdx.x*2 + half; r < NN; r += gridDim.x*2){
    float v = g_h[r*128 + c];
    s += v; q = fmaf(v, v, q);
  }
  ssum[t] = s; ssq[t] = q; __syncthreads();
  if(half == 0){
    atomicAdd(&g_stats[c],       ssum[t] + ssum[t+128]);
    atomicAdd(&g_stats[128 + c], ssq[t]  + ssq[t+128]);
  }
}

__global__ void k_params(const float* __restrict__ w, const float* __restrict__ b,
                         const float* __restrict__ ms){
  int c = threadIdx.x;
  if(c < HID){
    float mean = g_stats[c] * (1.f/(float)NN);
    float m = ms[c] * mean;
    float var = g_stats[128 + c] * (1.f/(float)NN) - 2.f*m*mean + m*m;
    float sc = w[c] * rsqrtf(var + EPSV);
    g_scale[c] = sc;
    g_shift[c] = b[c] - m*sc;
  }
}

__global__ void k_normelu(){
  int i = blockIdx.x*blockDim.x + threadIdx.x;
  if(i >= NN*32) return;                   // NN*HID/4 float4s
  int c4 = (i & 31) * 4;
  float4 v  = ((const float4*)g_h)[i];
  float4 sc = *(const float4*)(g_scale + c4);
  float4 sh = *(const float4*)(g_shift + c4);
  float4 o; float z;
  z = fmaf(v.x, sc.x, sh.x); o.x = z > 0.f ? z : (__expf(z) - 1.f);
  z = fmaf(v.y, sc.y, sh.y); o.y = z > 0.f ? z : (__expf(z) - 1.f);
  z = fmaf(v.z, sc.z, sh.z); o.z = z > 0.f ? z : (__expf(z) - 1.f);
  z = fmaf(v.w, sc.w, sh.w); o.w = z > 0.f ? z : (__expf(z) - 1.f);
  ((float4*)g_hn)[i] = o;
}

// ---------------- final FC: out[n] = x[n] . fcW + fcb ----------------
__global__ void k_fc(const float* __restrict__ fw, const float* __restrict__ fb,
                     float* __restrict__ out){
  int warp = (blockIdx.x*blockDim.x + threadIdx.x) >> 5;
  if(warp >= NN) return;
  int lane = threadIdx.x & 31;
  float4 v = *(const float4*)(g_x + warp*128 + lane*4);
  float4 w = *(const float4*)(fw + lane*4);
  float s = v.x*w.x + v.y*w.y + v.z*w.z + v.w*w.w;
  #pragma unroll
  for(int o = 16; o > 0; o >>= 1) s += __shfl_xor_sync(0xffffffffu, s, o);
  if(lane == 0) out[warp] = s + fb[0];
}

// ---------------- launcher ----------------
extern "C" void kernel_launch(void* const* d_in, const int* in_sizes, int n_in,
                              void* d_out, int out_size){
  const float* x     = (const float*)d_in[0];
  const int*   ei    = (const int*)  d_in[1];
  const float* Wl    = (const float*)d_in[2];
  const float* Wr    = (const float*)d_in[3];
  const float* att   = (const float*)d_in[4];
  const float* convb = (const float*)d_in[5];
  const float* gnw   = (const float*)d_in[6];
  const float* gnb   = (const float*)d_in[7];
  const float* gnms  = (const float*)d_in[8];
  const float* skW   = (const float*)d_in[9];
  const float* skb   = (const float*)d_in[10];
  const float* fcW   = (const float*)d_in[11];
  const float* fcb   = (const float*)d_in[12];
  float* out = (float*)d_out;

  // static graph structure: build CSR-by-dst once, reused by all layers
  k_copy_x  <<<(NN*32 + 255)/256, 256>>>(x);
  k_zero_cnt<<<(NN    + 255)/256, 256>>>();
  k_count   <<<(NT    + 255)/256, 256>>>(ei);
  k_scan    <<<1, 1024>>>();
  k_scatter <<<(NT    + 255)/256, 256>>>(ei);

  const int GEMM_GRID = (NN + 127)/128;      // 391
  for(int l = 0; l < 4; l++){
    k_gemm_xl<<<GEMM_GRID, 256>>>(Wl + l*HID*HID);
    k_gemm_xr<<<GEMM_GRID, 256>>>(Wr + l*HID*HID);
    k_gat<<<(NN*32 + 255)/256, 256>>>(att + l*HID, convb + l*HID);
    k_zero_stats<<<1, 256>>>();
    k_colsum<<<256, 256>>>();
    k_params<<<1, 128>>>(gnw + l*HID, gnb + l*HID, gnms + l*HID);
    k_normelu<<<(NN*32 + 255)/256, 256>>>();
    k_gemm_skip<<<GEMM_GRID, 256>>>(skW, skb);
  }
  k_fc<<<(NN*32 + 255)/256, 256>>>(fcW, fcb, out);
}

// round 3
// speedup vs baseline: 1.4087x; 1.4087x over previous
#include <cuda_runtime.h>
#include <cuda_bf16.h>
#include <math.h>
#include <cstdint>

#define NN 50000
#define NE 800000
#define NT 850000          // NE + NN self loops
#define HID 128
#define EPSV 1e-5f

// ================= scratch (device globals; no allocations) =================
__device__ __align__(16) float g_x [NN*HID];
__device__ __align__(16) float g_xl[NN*HID];
__device__ __align__(16) float g_xr[NN*HID];
__device__ __align__(16) float g_h [NN*HID];
__device__ __align__(16) __nv_bfloat16 g_ahi[NN*HID];   // x split hi
__device__ __align__(16) __nv_bfloat16 g_alo[NN*HID];   // x split lo
__device__ __align__(16) __nv_bfloat16 g_hhi[NN*HID];   // hn split hi
__device__ __align__(16) __nv_bfloat16 g_hlo[NN*HID];   // hn split lo
// weights: 4 layers x [k=128][n=256] ([Wl|Wr]) + skip [k=128][n=128]
__device__ __align__(16) __nv_bfloat16 g_wbhi[4*32768 + 16384];
__device__ __align__(16) __nv_bfloat16 g_wblo[4*32768 + 16384];
__device__ int   g_cnt[NN];
__device__ int   g_rowptr[NN+1];
__device__ int   g_fill[NN];
__device__ int   g_csrc[NT];
__device__ int   g_bsum[256];
__device__ int   g_bpre[256];
__device__ float g_stats[256];
__device__ float g_scale[HID];
__device__ float g_shift[HID];

// ================= mma.sync helpers (target-neutral PTX) =================
__device__ __forceinline__ uint32_t smem_u32(const void* p){
  uint32_t a;
  asm("{ .reg .u64 t; cvta.to.shared.u64 t, %1; cvt.u32.u64 %0, t; }" : "=r"(a) : "l"(p));
  return a;
}
__device__ __forceinline__ void ldm4(uint32_t* r, uint32_t a){
  asm volatile("ldmatrix.sync.aligned.m8n8.x4.shared.b16 {%0,%1,%2,%3}, [%4];"
    : "=r"(r[0]),"=r"(r[1]),"=r"(r[2]),"=r"(r[3]) : "r"(a));
}
__device__ __forceinline__ void ldm4t(uint32_t* r, uint32_t a){
  asm volatile("ldmatrix.sync.aligned.m8n8.x4.trans.shared.b16 {%0,%1,%2,%3}, [%4];"
    : "=r"(r[0]),"=r"(r[1]),"=r"(r[2]),"=r"(r[3]) : "r"(a));
}
__device__ __forceinline__ void mma_bf16(float* c, const uint32_t* a, const uint32_t* b){
  asm volatile("mma.sync.aligned.m16n8k16.row.col.f32.bf16.bf16.f32 "
    "{%0,%1,%2,%3}, {%4,%5,%6,%7}, {%8,%9}, {%0,%1,%2,%3};"
    : "+f"(c[0]),"+f"(c[1]),"+f"(c[2]),"+f"(c[3])
    : "r"(a[0]),"r"(a[1]),"r"(a[2]),"r"(a[3]), "r"(b[0]),"r"(b[1]));
}
// A tile smem: 128 rows x 256B, xor-swizzled 16B units within 128B halves
__device__ __forceinline__ uint32_t swA(int r, int c2){
  int u = c2 >> 4;
  u = (u & 8) | ((u ^ (r & 7)) & 7);
  return (uint32_t)(r*256 + (u << 4) + (c2 & 15));
}
template<int RS>   // B tile smem: 128 rows x RS bytes
__device__ __forceinline__ uint32_t swB(int r, int c2){
  int u = c2 >> 4;
  u = (u & ~7) | ((u ^ (r & 7)) & 7);
  return (uint32_t)(r*RS + (u << 4) + (c2 & 15));
}

// ================= setup =================
__global__ void k_init(const float* __restrict__ x){
  int i = blockIdx.x*blockDim.x + threadIdx.x;
  if(i >= NN*32) return;
  float4 v = ((const float4*)x)[i];
  ((float4*)g_x)[i] = v;
  __nv_bfloat162 h0, h1, l0, l1;
  h0.x = __float2bfloat16_rn(v.x); h0.y = __float2bfloat16_rn(v.y);
  h1.x = __float2bfloat16_rn(v.z); h1.y = __float2bfloat16_rn(v.w);
  l0.x = __float2bfloat16_rn(v.x - __bfloat162float(h0.x));
  l0.y = __float2bfloat16_rn(v.y - __bfloat162float(h0.y));
  l1.x = __float2bfloat16_rn(v.z - __bfloat162float(h1.x));
  l1.y = __float2bfloat16_rn(v.w - __bfloat162float(h1.y));
  ((__nv_bfloat162*)g_ahi)[2*i] = h0; ((__nv_bfloat162*)g_ahi)[2*i+1] = h1;
  ((__nv_bfloat162*)g_alo)[2*i] = l0; ((__nv_bfloat162*)g_alo)[2*i+1] = l1;
}
__global__ void k_zero_cnt(){
  int i = blockIdx.x*blockDim.x + threadIdx.x;
  if(i < NN) g_cnt[i] = 0;
}
__global__ void k_count(const int* __restrict__ ei){
  int i = blockIdx.x*blockDim.x + threadIdx.x;
  if(i >= NT) return;
  int d = (i < NE) ? ei[NE + i] : (i - NE);
  atomicAdd(&g_cnt[d], 1);
}
#define SCAN_B 196
__global__ void k_blocksum(){
  __shared__ int sh[256];
  int t = threadIdx.x;
  int i = blockIdx.x*256 + t;
  sh[t] = (i < NN) ? g_cnt[i] : 0; __syncthreads();
  #pragma unroll
  for(int off = 128; off > 0; off >>= 1){
    if(t < off) sh[t] += sh[t+off];
    __syncthreads();
  }
  if(t == 0) g_bsum[blockIdx.x] = sh[0];
}
__global__ void k_scan_bsum(){
  __shared__ int sh[256];
  int t = threadIdx.x;
  int v = (t < SCAN_B) ? g_bsum[t] : 0;
  sh[t] = v; __syncthreads();
  #pragma unroll
  for(int off = 1; off < 256; off <<= 1){
    int u = (t >= off) ? sh[t-off] : 0;
    __syncthreads(); sh[t] += u; __syncthreads();
  }
  if(t < SCAN_B) g_bpre[t] = sh[t] - v;
  if(t == 255) g_rowptr[NN] = sh[255];
}
__global__ void k_rowptr(){
  __shared__ int sh[256];
  int t = threadIdx.x;
  int i = blockIdx.x*256 + t;
  int v = (i < NN) ? g_cnt[i] : 0;
  sh[t] = v; __syncthreads();
  #pragma unroll
  for(int off = 1; off < 256; off <<= 1){
    int u = (t >= off) ? sh[t-off] : 0;
    __syncthreads(); sh[t] += u; __syncthreads();
  }
  if(i < NN){
    int e = sh[t] - v + g_bpre[blockIdx.x];
    g_rowptr[i] = e; g_fill[i] = e;
  }
}
__global__ void k_scatter(const int* __restrict__ ei){
  int i = blockIdx.x*blockDim.x + threadIdx.x;
  if(i >= NT) return;
  int s, d;
  if(i < NE){ s = ei[i]; d = ei[NE + i]; }
  else      { s = d = i - NE; }
  int pos = atomicAdd(&g_fill[d], 1);
  g_csrc[pos] = s;
}
// weights -> bf16 hi/lo, layout [k][n] row-major; LR: n<128 from Wl, n>=128 from Wr
__global__ void k_cvt_w(const float* __restrict__ Wl, const float* __restrict__ Wr,
                        const float* __restrict__ skW){
  int i = blockIdx.x*blockDim.x + threadIdx.x;
  if(i >= 4*32768 + 16384) return;
  float v;
  if(i < 4*32768){
    int l = i >> 15, rem = i & 32767, k = rem >> 8, n = rem & 255;
    v = (n < 128) ? Wl[l*16384 + k*128 + n] : Wr[l*16384 + k*128 + (n-128)];
  } else {
    int j = i - 4*32768;
    v = skW[j];
  }
  __nv_bfloat16 h = __float2bfloat16_rn(v);
  g_wbhi[i] = h;
  g_wblo[i] = __float2bfloat16_rn(v - __bfloat162float(h));
}

// ================= tensor-core GEMM core =================
// C[M, NCOLS] = A[M,128] @ B[128,NCOLS], split-precision bf16x3, fp32 accum.
// block: (NCOLS/32)*2 warps; warp tile 64m x 32n; K=128 fully smem-resident.
template<int NCOLS, bool SKIP>
__device__ __forceinline__ void mma_core(
  const __nv_bfloat16* __restrict__ Ahi_g, const __nv_bfloat16* __restrict__ Alo_g,
  const __nv_bfloat16* __restrict__ Bhi_g, const __nv_bfloat16* __restrict__ Blo_g,
  const float* __restrict__ bias)
{
  extern __shared__ __align__(16) char smem[];
  constexpr int WN = NCOLS/32;          // warps along n
  constexpr int TB = WN*2*32;           // threads
  constexpr int BB = NCOLS*256;         // B tile bytes
  constexpr int BHI = 65536;
  const int tid = threadIdx.x, wid = tid >> 5, lane = tid & 31;
  const int warp_m = wid / WN, warp_n = wid % WN;
  const int bm = blockIdx.x * 128;
  const uint32_t sb = smem_u32(smem);

  // ---- fill smem ----
  for(int ch = tid; ch < 2048; ch += TB){
    int r = ch >> 4, c2 = (ch & 15) << 4;
    int grow = bm + r;
    uint4 vh = make_uint4(0,0,0,0), vl = vh;
    if(grow < NN){
      vh = *(const uint4*)(Ahi_g + grow*128 + (c2 >> 1));
      vl = *(const uint4*)(Alo_g + grow*128 + (c2 >> 1));
    }
    uint32_t off = swA(r, c2);
    *(uint4*)(smem + off)         = vh;
    *(uint4*)(smem + 32768 + off) = vl;
  }
  constexpr int UPR = NCOLS/8;           // 16B units per B row
  for(int ch = tid; ch < NCOLS*16; ch += TB){
    int r = ch / UPR, c2 = (ch % UPR) * 16;
    uint32_t off = swB<NCOLS*2>(r, c2);
    *(uint4*)(smem + BHI + off)      = *(const uint4*)(Bhi_g + r*NCOLS + (c2 >> 1));
    *(uint4*)(smem + BHI + BB + off) = *(const uint4*)(Blo_g + r*NCOLS + (c2 >> 1));
  }
  __syncthreads();

  // ---- compute ----
  float acc[4][4][4];
  #pragma unroll
  for(int mt = 0; mt < 4; mt++)
    #pragma unroll
    for(int nt = 0; nt < 4; nt++)
      #pragma unroll
      for(int r = 0; r < 4; r++) acc[mt][nt][r] = 0.f;

  const int arow = warp_m*64 + (lane & 15);
  const int ac2b = (lane >> 4) << 4;
  const int bgrp = lane >> 3;
  const int bkr  = ((bgrp & 1) << 3) + (lane & 7);
  const int bnc  = warp_n*32 + ((bgrp >> 1) << 3);

  #pragma unroll
  for(int ks = 0; ks < 8; ks++){
    uint32_t bh[4][2], bl[4][2], tmp[4];
    #pragma unroll
    for(int np = 0; np < 2; np++){
      uint32_t boff = swB<NCOLS*2>(ks*16 + bkr, (bnc + np*16)*2);
      ldm4t(tmp, sb + BHI + boff);
      bh[np*2][0]=tmp[0]; bh[np*2][1]=tmp[1]; bh[np*2+1][0]=tmp[2]; bh[np*2+1][1]=tmp[3];
      ldm4t(tmp, sb + BHI + BB + boff);
      bl[np*2][0]=tmp[0]; bl[np*2][1]=tmp[1]; bl[np*2+1][0]=tmp[2]; bl[np*2+1][1]=tmp[3];
    }
    uint32_t a[4][4];
    #pragma unroll
    for(int mt = 0; mt < 4; mt++)
      ldm4(a[mt], sb + swA(arow + mt*16, ks*32 + ac2b));          // A hi
    #pragma unroll
    for(int mt = 0; mt < 4; mt++)
      #pragma unroll
      for(int nt = 0; nt < 4; nt++){
        mma_bf16(acc[mt][nt], a[mt], bh[nt]);                     // Ahi*Bhi
        mma_bf16(acc[mt][nt], a[mt], bl[nt]);                     // Ahi*Blo
      }
    #pragma unroll
    for(int mt = 0; mt < 4; mt++)
      ldm4(a[mt], sb + 32768 + swA(arow + mt*16, ks*32 + ac2b));  // A lo
    #pragma unroll
    for(int mt = 0; mt < 4; mt++)
      #pragma unroll
      for(int nt = 0; nt < 4; nt++)
        mma_bf16(acc[mt][nt], a[mt], bh[nt]);                     // Alo*Bhi
  }

  // ---- epilogue ----
  #pragma unroll
  for(int mt = 0; mt < 4; mt++){
    int r0 = bm + warp_m*64 + mt*16 + (lane >> 2);
    #pragma unroll
    for(int nt = 0; nt < 4; nt++){
      int colg = warp_n*32 + nt*8 + (lane & 3)*2;
      #pragma unroll
      for(int half = 0; half < 2; half++){
        int grow = r0 + half*8;
        if(grow >= NN) continue;
        float v0 = acc[mt][nt][half*2], v1 = acc[mt][nt][half*2+1];
        if(!SKIP){
          float* outp; int col;
          if(colg < 128){ outp = g_xl; col = colg; } else { outp = g_xr; col = colg - 128; }
          *(float2*)(outp + grow*128 + col) = make_float2(v0, v1);
        } else {
          int col = colg;
          float2 old = *(const float2*)(g_x + grow*128 + col);
          v0 += bias[col]   + old.x;
          v1 += bias[col+1] + old.y;
          *(float2*)(g_x + grow*128 + col) = make_float2(v0, v1);
          __nv_bfloat162 h, l;
          h.x = __float2bfloat16_rn(v0); h.y = __float2bfloat16_rn(v1);
          l.x = __float2bfloat16_rn(v0 - __bfloat162float(h.x));
          l.y = __float2bfloat16_rn(v1 - __bfloat162float(h.y));
          *(__nv_bfloat162*)(g_ahi + grow*128 + col) = h;
          *(__nv_bfloat162*)(g_alo + grow*128 + col) = l;
        }
      }
    }
  }
}

__global__ void __launch_bounds__(512, 1) k_mma_lr(int layer){
  mma_core<256, false>(g_ahi, g_alo, g_wbhi + layer*32768, g_wblo + layer*32768, nullptr);
}
__global__ void __launch_bounds__(256, 1) k_mma_skip(const float* __restrict__ bias){
  mma_core<128, true>(g_hhi, g_hlo, g_wbhi + 4*32768, g_wblo + 4*32768, bias);
}

// ================= GATv2 attention + online-softmax aggregation =================
__device__ __forceinline__ float lrelu(float v){ return v > 0.f ? v : 0.2f*v; }

__global__ void k_gat(const float* __restrict__ att, const float* __restrict__ convb){
  int warp = (blockIdx.x*blockDim.x + threadIdx.x) >> 5;
  if(warp >= NN) return;
  int lane = threadIdx.x & 31;
  int c4 = lane * 4;
  const float4 xr4 = *(const float4*)(g_xr + warp*128 + c4);
  const float4 at4 = *(const float4*)(att + c4);
  int pb = g_rowptr[warp], pe = g_rowptr[warp+1];

  float m = -3.4e38f, ds = 0.f;
  float a0 = 0.f, a1 = 0.f, a2 = 0.f, a3 = 0.f;

  for(int p = pb; p < pe; p++){
    int s = g_csrc[p];
    float4 v = *(const float4*)(g_xl + s*128 + c4);
    float t = lrelu(v.x + xr4.x)*at4.x + lrelu(v.y + xr4.y)*at4.y
            + lrelu(v.z + xr4.z)*at4.z + lrelu(v.w + xr4.w)*at4.w;
    t += __shfl_xor_sync(0xffffffffu, t, 4);
    t += __shfl_xor_sync(0xffffffffu, t, 2);
    t += __shfl_xor_sync(0xffffffffu, t, 1);
    if(t <= m){
      float a = __expf(t - m);
      ds += a;
      a0 = fmaf(a, v.x, a0); a1 = fmaf(a, v.y, a1);
      a2 = fmaf(a, v.z, a2); a3 = fmaf(a, v.w, a3);
    } else {
      float f = __expf(m - t);
      ds = fmaf(ds, f, 1.f);
      a0 = fmaf(a0, f, v.x); a1 = fmaf(a1, f, v.y);
      a2 = fmaf(a2, f, v.z); a3 = fmaf(a3, f, v.w);
      m = t;
    }
  }
  float inv = 1.f / ds;
  const float4 bb = *(const float4*)(convb + c4);
  float4 o;
  o.x = fmaf(a0, inv, bb.x); o.y = fmaf(a1, inv, bb.y);
  o.z = fmaf(a2, inv, bb.z); o.w = fmaf(a3, inv, bb.w);
  *(float4*)(g_h + warp*128 + c4) = o;
}

// ================= GraphNorm =================
__global__ void k_zero_stats(){
  int i = threadIdx.x;
  if(i < 256) g_stats[i] = 0.f;
}
__global__ void k_colsum(){
  __shared__ float ssum[256], ssq[256];
  int t = threadIdx.x; int c = t & 127; int half = t >> 7;
  float s = 0.f, q = 0.f;
  for(int r = blockIdx.x*2 + half; r < NN; r += gridDim.x*2){
    float v = g_h[r*128 + c];
    s += v; q = fmaf(v, v, q);
  }
  ssum[t] = s; ssq[t] = q; __syncthreads();
  if(half == 0){
    atomicAdd(&g_stats[c],       ssum[t] + ssum[t+128]);
    atomicAdd(&g_stats[128 + c], ssq[t]  + ssq[t+128]);
  }
}
__global__ void k_params(const float* __restrict__ w, const float* __restrict__ b,
                         const float* __restrict__ ms){
  int c = threadIdx.x;
  if(c < HID){
    float mean = g_stats[c] * (1.f/(float)NN);
    float m = ms[c] * mean;
    float var = g_stats[128 + c] * (1.f/(float)NN) - 2.f*m*mean + m*m;
    float sc = w[c] * rsqrtf(var + EPSV);
    g_scale[c] = sc;
    g_shift[c] = b[c] - m*sc;
  }
}
// norm + elu, writing bf16 hi/lo splits of hn directly
__global__ void k_normelu(){
  int i = blockIdx.x*blockDim.x + threadIdx.x;
  if(i >= NN*32) return;
  int c4 = (i & 31) * 4;
  float4 v  = ((const float4*)g_h)[i];
  float4 sc = *(const float4*)(g_scale + c4);
  float4 sh = *(const float4*)(g_shift + c4);
  float4 o; float z;
  z = fmaf(v.x, sc.x, sh.x); o.x = z > 0.f ? z : (__expf(z) - 1.f);
  z = fmaf(v.y, sc.y, sh.y); o.y = z > 0.f ? z : (__expf(z) - 1.f);
  z = fmaf(v.z, sc.z, sh.z); o.z = z > 0.f ? z : (__expf(z) - 1.f);
  z = fmaf(v.w, sc.w, sh.w); o.w = z > 0.f ? z : (__expf(z) - 1.f);
  __nv_bfloat162 h0, h1, l0, l1;
  h0.x = __float2bfloat16_rn(o.x); h0.y = __float2bfloat16_rn(o.y);
  h1.x = __float2bfloat16_rn(o.z); h1.y = __float2bfloat16_rn(o.w);
  l0.x = __float2bfloat16_rn(o.x - __bfloat162float(h0.x));
  l0.y = __float2bfloat16_rn(o.y - __bfloat162float(h0.y));
  l1.x = __float2bfloat16_rn(o.z - __bfloat162float(h1.x));
  l1.y = __float2bfloat16_rn(o.w - __bfloat162float(h1.y));
  ((__nv_bfloat162*)g_hhi)[2*i] = h0; ((__nv_bfloat162*)g_hhi)[2*i+1] = h1;
  ((__nv_bfloat162*)g_hlo)[2*i] = l0; ((__nv_bfloat162*)g_hlo)[2*i+1] = l1;
}

// ================= final FC =================
__global__ void k_fc(const float* __restrict__ fw, const float* __restrict__ fb,
                     float* __restrict__ out){
  int warp = (blockIdx.x*blockDim.x + threadIdx.x) >> 5;
  if(warp >= NN) return;
  int lane = threadIdx.x & 31;
  float4 v = *(const float4*)(g_x + warp*128 + lane*4);
  float4 w = *(const float4*)(fw + lane*4);
  float s = v.x*w.x + v.y*w.y + v.z*w.z + v.w*w.w;
  #pragma unroll
  for(int o = 16; o > 0; o >>= 1) s += __shfl_xor_sync(0xffffffffu, s, o);
  if(lane == 0) out[warp] = s + fb[0];
}

// ================= launcher =================
extern "C" void kernel_launch(void* const* d_in, const int* in_sizes, int n_in,
                              void* d_out, int out_size){
  const float* x     = (const float*)d_in[0];
  const int*   ei    = (const int*)  d_in[1];
  const float* Wl    = (const float*)d_in[2];
  const float* Wr    = (const float*)d_in[3];
  const float* att   = (const float*)d_in[4];
  const float* convb = (const float*)d_in[5];
  const float* gnw   = (const float*)d_in[6];
  const float* gnb   = (const float*)d_in[7];
  const float* gnms  = (const float*)d_in[8];
  const float* skW   = (const float*)d_in[9];
  const float* skb   = (const float*)d_in[10];
  const float* fcW   = (const float*)d_in[11];
  const float* fcb   = (const float*)d_in[12];
  float* out = (float*)d_out;

  static int cfg_done = 0;
  if(!cfg_done){
    cudaFuncSetAttribute(k_mma_lr,   cudaFuncAttributeMaxDynamicSharedMemorySize, 196608);
    cudaFuncSetAttribute(k_mma_skip, cudaFuncAttributeMaxDynamicSharedMemorySize, 131072);
    cfg_done = 1;
  }

  // setup: x copy+split, CSR build, weight split
  k_init     <<<(NN*32 + 255)/256, 256>>>(x);
  k_zero_cnt <<<(NN    + 255)/256, 256>>>();
  k_count    <<<(NT    + 255)/256, 256>>>(ei);
  k_blocksum <<<SCAN_B, 256>>>();
  k_scan_bsum<<<1, 256>>>();
  k_rowptr   <<<SCAN_B, 256>>>();
  k_scatter  <<<(NT    + 255)/256, 256>>>(ei);
  k_cvt_w    <<<(4*32768 + 16384 + 255)/256, 256>>>(Wl, Wr, skW);

  const int MMA_GRID = (NN + 127)/128;       // 391
  for(int l = 0; l < 4; l++){
    k_mma_lr   <<<MMA_GRID, 512, 196608>>>(l);                 // [xl|xr] = x @ [Wl|Wr]
    k_gat      <<<(NN*32 + 255)/256, 256>>>(att + l*HID, convb + l*HID);
    k_zero_stats<<<1, 256>>>();
    k_colsum   <<<256, 256>>>();
    k_params   <<<1, 128>>>(gnw + l*HID, gnb + l*HID, gnms + l*HID);
    k_normelu  <<<(NN*32 + 255)/256, 256>>>();
    k_mma_skip <<<MMA_GRID, 256, 131072>>>(skb);               // x += hn @ skW + b (+ split)
  }
  k_fc<<<(NN*32 + 255)/256, 256>>>(fcW, fcb, out);
}

// round 4
// speedup vs baseline: 1.5749x; 1.1180x over previous
#include <cuda_runtime.h>
#include <cuda_bf16.h>
#include <cuda_fp16.h>
#include <math.h>
#include <cstdint>

#define NN 50000
#define NE 800000
#define NT 850000          // NE + NN self loops
#define HID 128
#define EPSV 1e-5f

// ================= scratch (device globals; no allocations) =================
__device__ __align__(16) float g_x [NN*HID];
__device__ __align__(16) float g_xr[NN*HID];
__device__ __align__(16) float g_h [NN*HID];
__device__ __align__(16) __half g_xlh[NN*HID];          // xl in fp16 (gather table)
__device__ __align__(16) __nv_bfloat16 g_ahi[NN*HID];   // x split hi
__device__ __align__(16) __nv_bfloat16 g_alo[NN*HID];   // x split lo
// weights: 4 layers x [k=128][n=256] ([Wl|Wr]) + skip [k=128][n=128]
__device__ __align__(16) __nv_bfloat16 g_wbhi[4*32768 + 16384];
__device__ __align__(16) __nv_bfloat16 g_wblo[4*32768 + 16384];
__device__ int   g_cnt[NN];
__device__ int   g_rowptr[NN+1];
__device__ int   g_fill[NN];
__device__ int   g_csrc[NT];
__device__ int   g_bsum[256];
__device__ int   g_bpre[256];
__device__ float g_stats[256];      // [0:128) sum, [128:256) sumsq ; reset by k_params
__device__ float g_scale[HID];
__device__ float g_shift[HID];

// ================= mma.sync helpers (target-neutral PTX) =================
__device__ __forceinline__ uint32_t smem_u32(const void* p){
  uint32_t a;
  asm("{ .reg .u64 t; cvta.to.shared.u64 t, %1; cvt.u32.u64 %0, t; }" : "=r"(a) : "l"(p));
  return a;
}
__device__ __forceinline__ void ldm4(uint32_t* r, uint32_t a){
  asm volatile("ldmatrix.sync.aligned.m8n8.x4.shared.b16 {%0,%1,%2,%3}, [%4];"
    : "=r"(r[0]),"=r"(r[1]),"=r"(r[2]),"=r"(r[3]) : "r"(a));
}
__device__ __forceinline__ void ldm4t(uint32_t* r, uint32_t a){
  asm volatile("ldmatrix.sync.aligned.m8n8.x4.trans.shared.b16 {%0,%1,%2,%3}, [%4];"
    : "=r"(r[0]),"=r"(r[1]),"=r"(r[2]),"=r"(r[3]) : "r"(a));
}
__device__ __forceinline__ void mma_bf16(float* c, const uint32_t* a, const uint32_t* b){
  asm volatile("mma.sync.aligned.m16n8k16.row.col.f32.bf16.bf16.f32 "
    "{%0,%1,%2,%3}, {%4,%5,%6,%7}, {%8,%9}, {%0,%1,%2,%3};"
    : "+f"(c[0]),"+f"(c[1]),"+f"(c[2]),"+f"(c[3])
    : "r"(a[0]),"r"(a[1]),"r"(a[2]),"r"(a[3]), "r"(b[0]),"r"(b[1]));
}
__device__ __forceinline__ uint32_t swA(int r, int c2){
  int u = c2 >> 4;
  u = (u & 8) | ((u ^ (r & 7)) & 7);
  return (uint32_t)(r*256 + (u << 4) + (c2 & 15));
}
template<int RS>
__device__ __forceinline__ uint32_t swB(int r, int c2){
  int u = c2 >> 4;
  u = (u & ~7) | ((u ^ (r & 7)) & 7);
  return (uint32_t)(r*RS + (u << 4) + (c2 & 15));
}

// ================= setup =================
__global__ void k_init(const float* __restrict__ x){
  int i = blockIdx.x*blockDim.x + threadIdx.x;
  if(i < NN) g_cnt[i] = 0;
  if(i >= NN*32) return;
  float4 v = ((const float4*)x)[i];
  ((float4*)g_x)[i] = v;
  __nv_bfloat162 h0, h1, l0, l1;
  h0.x = __float2bfloat16_rn(v.x); h0.y = __float2bfloat16_rn(v.y);
  h1.x = __float2bfloat16_rn(v.z); h1.y = __float2bfloat16_rn(v.w);
  l0.x = __float2bfloat16_rn(v.x - __bfloat162float(h0.x));
  l0.y = __float2bfloat16_rn(v.y - __bfloat162float(h0.y));
  l1.x = __float2bfloat16_rn(v.z - __bfloat162float(h1.x));
  l1.y = __float2bfloat16_rn(v.w - __bfloat162float(h1.y));
  ((__nv_bfloat162*)g_ahi)[2*i] = h0; ((__nv_bfloat162*)g_ahi)[2*i+1] = h1;
  ((__nv_bfloat162*)g_alo)[2*i] = l0; ((__nv_bfloat162*)g_alo)[2*i+1] = l1;
}
__global__ void k_count(const int* __restrict__ ei){
  int i = blockIdx.x*blockDim.x + threadIdx.x;
  if(i >= NT) return;
  int d = (i < NE) ? ei[NE + i] : (i - NE);
  atomicAdd(&g_cnt[d], 1);
}
#define SCAN_B 196
__global__ void k_blocksum(){
  __shared__ int sh[256];
  int t = threadIdx.x;
  int i = blockIdx.x*256 + t;
  sh[t] = (i < NN) ? g_cnt[i] : 0; __syncthreads();
  #pragma unroll
  for(int off = 128; off > 0; off >>= 1){
    if(t < off) sh[t] += sh[t+off];
    __syncthreads();
  }
  if(t == 0) g_bsum[blockIdx.x] = sh[0];
}
__global__ void k_scan_bsum(){
  __shared__ int sh[256];
  int t = threadIdx.x;
  int v = (t < SCAN_B) ? g_bsum[t] : 0;
  sh[t] = v; __syncthreads();
  #pragma unroll
  for(int off = 1; off < 256; off <<= 1){
    int u = (t >= off) ? sh[t-off] : 0;
    __syncthreads(); sh[t] += u; __syncthreads();
  }
  if(t < SCAN_B) g_bpre[t] = sh[t] - v;
  if(t == 255) g_rowptr[NN] = sh[255];
}
__global__ void k_rowptr(){
  __shared__ int sh[256];
  int t = threadIdx.x;
  int i = blockIdx.x*256 + t;
  int v = (i < NN) ? g_cnt[i] : 0;
  sh[t] = v; __syncthreads();
  #pragma unroll
  for(int off = 1; off < 256; off <<= 1){
    int u = (t >= off) ? sh[t-off] : 0;
    __syncthreads(); sh[t] += u; __syncthreads();
  }
  if(i < NN){
    int e = sh[t] - v + g_bpre[blockIdx.x];
    g_rowptr[i] = e; g_fill[i] = e;
  }
}
__global__ void k_scatter(const int* __restrict__ ei){
  int i = blockIdx.x*blockDim.x + threadIdx.x;
  if(i >= NT) return;
  int s, d;
  if(i < NE){ s = ei[i]; d = ei[NE + i]; }
  else      { s = d = i - NE; }
  int pos = atomicAdd(&g_fill[d], 1);
  g_csrc[pos] = s;
}
__global__ void k_cvt_w(const float* __restrict__ Wl, const float* __restrict__ Wr,
                        const float* __restrict__ skW){
  int i = blockIdx.x*blockDim.x + threadIdx.x;
  if(i >= 4*32768 + 16384) return;
  float v;
  if(i < 4*32768){
    int l = i >> 15, rem = i & 32767, k = rem >> 8, n = rem & 255;
    v = (n < 128) ? Wl[l*16384 + k*128 + n] : Wr[l*16384 + k*128 + (n-128)];
  } else {
    v = skW[i - 4*32768];
  }
  __nv_bfloat16 h = __float2bfloat16_rn(v);
  g_wbhi[i] = h;
  g_wblo[i] = __float2bfloat16_rn(v - __bfloat162float(h));
}

// ================= tensor-core GEMM core =================
// C[M,NCOLS] = A[M,128] @ B[128,NCOLS]; split bf16x3, fp32 accum; K fully resident.
// SKIP=false: A = x splits; out -> g_xlh (fp16, n<128) / g_xr (fp32, n>=128)
// SKIP=true : A = norm+elu(g_h) computed inline; out -> g_x += .. ; also rewrite x splits
template<int NCOLS, bool SKIP>
__device__ __forceinline__ void mma_core(
  const __nv_bfloat16* __restrict__ Bhi_g, const __nv_bfloat16* __restrict__ Blo_g,
  const float* __restrict__ bias)
{
  extern __shared__ __align__(16) char smem[];
  constexpr int WN = NCOLS/32;
  constexpr int TB = WN*2*32;
  constexpr int BB = NCOLS*256;
  constexpr int BHI = 65536;
  const int tid = threadIdx.x, wid = tid >> 5, lane = tid & 31;
  const int warp_m = wid / WN, warp_n = wid % WN;
  const int bm = blockIdx.x * 128;
  const uint32_t sb = smem_u32(smem);

  // ---- fill A smem ----
  for(int ch = tid; ch < 2048; ch += TB){
    int r = ch >> 4, c2 = (ch & 15) << 4;   // c2: byte col (16B chunk), 8 elems
    int grow = bm + r;
    uint32_t off = swA(r, c2);
    if(!SKIP){
      uint4 vh = make_uint4(0,0,0,0), vl = vh;
      if(grow < NN){
        vh = *(const uint4*)(g_ahi + grow*128 + (c2 >> 1));
        vl = *(const uint4*)(g_alo + grow*128 + (c2 >> 1));
      }
      *(uint4*)(smem + off)         = vh;
      *(uint4*)(smem + 32768 + off) = vl;
    } else {
      int c = c2 >> 1;                       // element col base (step 8)
      __nv_bfloat162 hh[4], ll[4];
      if(grow < NN){
        #pragma unroll
        for(int q = 0; q < 2; q++){
          float4 v  = *(const float4*)(g_h + grow*128 + c + q*4);
          float4 sc = *(const float4*)(g_scale + c + q*4);
          float4 sh = *(const float4*)(g_shift + c + q*4);
          float z0 = fmaf(v.x, sc.x, sh.x); z0 = z0 > 0.f ? z0 : (__expf(z0) - 1.f);
          float z1 = fmaf(v.y, sc.y, sh.y); z1 = z1 > 0.f ? z1 : (__expf(z1) - 1.f);
          float z2 = fmaf(v.z, sc.z, sh.z); z2 = z2 > 0.f ? z2 : (__expf(z2) - 1.f);
          float z3 = fmaf(v.w, sc.w, sh.w); z3 = z3 > 0.f ? z3 : (__expf(z3) - 1.f);
          hh[q*2].x   = __float2bfloat16_rn(z0); hh[q*2].y   = __float2bfloat16_rn(z1);
          hh[q*2+1].x = __float2bfloat16_rn(z2); hh[q*2+1].y = __float2bfloat16_rn(z3);
          ll[q*2].x   = __float2bfloat16_rn(z0 - __bfloat162float(hh[q*2].x));
          ll[q*2].y   = __float2bfloat16_rn(z1 - __bfloat162float(hh[q*2].y));
          ll[q*2+1].x = __float2bfloat16_rn(z2 - __bfloat162float(hh[q*2+1].x));
          ll[q*2+1].y = __float2bfloat16_rn(z3 - __bfloat162float(hh[q*2+1].y));
        }
      } else {
        #pragma unroll
        for(int q = 0; q < 4; q++){ hh[q].x = hh[q].y = __float2bfloat16_rn(0.f); ll[q] = hh[q]; }
      }
      *(uint4*)(smem + off)         = *(uint4*)hh;
      *(uint4*)(smem + 32768 + off) = *(uint4*)ll;
    }
  }
  // ---- fill B smem ----
  constexpr int UPR = NCOLS/8;
  for(int ch = tid; ch < NCOLS*16; ch += TB){
    int r = ch / UPR, c2 = (ch % UPR) * 16;
    uint32_t off = swB<NCOLS*2>(r, c2);
    *(uint4*)(smem + BHI + off)      = *(const uint4*)(Bhi_g + r*NCOLS + (c2 >> 1));
    *(uint4*)(smem + BHI + BB + off) = *(const uint4*)(Blo_g + r*NCOLS + (c2 >> 1));
  }
  __syncthreads();

  // ---- compute ----
  float acc[4][4][4];
  #pragma unroll
  for(int mt = 0; mt < 4; mt++)
    #pragma unroll
    for(int nt = 0; nt < 4; nt++)
      #pragma unroll
      for(int r = 0; r < 4; r++) acc[mt][nt][r] = 0.f;

  const int arow = warp_m*64 + (lane & 15);
  const int ac2b = (lane >> 4) << 4;
  const int bgrp = lane >> 3;
  const int bkr  = ((bgrp & 1) << 3) + (lane & 7);
  const int bnc  = warp_n*32 + ((bgrp >> 1) << 3);

  #pragma unroll
  for(int ks = 0; ks < 8; ks++){
    uint32_t bh[4][2], bl[4][2], tmp[4];
    #pragma unroll
    for(int np = 0; np < 2; np++){
      uint32_t boff = swB<NCOLS*2>(ks*16 + bkr, (bnc + np*16)*2);
      ldm4t(tmp, sb + BHI + boff);
      bh[np*2][0]=tmp[0]; bh[np*2][1]=tmp[1]; bh[np*2+1][0]=tmp[2]; bh[np*2+1][1]=tmp[3];
      ldm4t(tmp, sb + BHI + BB + boff);
      bl[np*2][0]=tmp[0]; bl[np*2][1]=tmp[1]; bl[np*2+1][0]=tmp[2]; bl[np*2+1][1]=tmp[3];
    }
    uint32_t a[4][4];
    #pragma unroll
    for(int mt = 0; mt < 4; mt++)
      ldm4(a[mt], sb + swA(arow + mt*16, ks*32 + ac2b));
    #pragma unroll
    for(int mt = 0; mt < 4; mt++)
      #pragma unroll
      for(int nt = 0; nt < 4; nt++){
        mma_bf16(acc[mt][nt], a[mt], bh[nt]);
        mma_bf16(acc[mt][nt], a[mt], bl[nt]);
      }
    #pragma unroll
    for(int mt = 0; mt < 4; mt++)
      ldm4(a[mt], sb + 32768 + swA(arow + mt*16, ks*32 + ac2b));
    #pragma unroll
    for(int mt = 0; mt < 4; mt++)
      #pragma unroll
      for(int nt = 0; nt < 4; nt++)
        mma_bf16(acc[mt][nt], a[mt], bh[nt]);
  }

  // ---- epilogue ----
  #pragma unroll
  for(int mt = 0; mt < 4; mt++){
    int r0 = bm + warp_m*64 + mt*16 + (lane >> 2);
    #pragma unroll
    for(int nt = 0; nt < 4; nt++){
      int colg = warp_n*32 + nt*8 + (lane & 3)*2;
      #pragma unroll
      for(int half = 0; half < 2; half++){
        int grow = r0 + half*8;
        if(grow >= NN) continue;
        float v0 = acc[mt][nt][half*2], v1 = acc[mt][nt][half*2+1];
        if(!SKIP){
          if(colg < 128){
            *(__half2*)(g_xlh + grow*128 + colg) = __floats2half2_rn(v0, v1);
          } else {
            *(float2*)(g_xr + grow*128 + (colg - 128)) = make_float2(v0, v1);
          }
        } else {
          int col = colg;
          float2 old = *(const float2*)(g_x + grow*128 + col);
          v0 += bias[col]   + old.x;
          v1 += bias[col+1] + old.y;
          *(float2*)(g_x + grow*128 + col) = make_float2(v0, v1);
          __nv_bfloat162 h, l;
          h.x = __float2bfloat16_rn(v0); h.y = __float2bfloat16_rn(v1);
          l.x = __float2bfloat16_rn(v0 - __bfloat162float(h.x));
          l.y = __float2bfloat16_rn(v1 - __bfloat162float(h.y));
          *(__nv_bfloat162*)(g_ahi + grow*128 + col) = h;
          *(__nv_bfloat162*)(g_alo + grow*128 + col) = l;
        }
      }
    }
  }
}

__global__ void __launch_bounds__(512, 1) k_mma_lr(int layer){
  mma_core<256, false>(g_wbhi + layer*32768, g_wblo + layer*32768, nullptr);
}
__global__ void __launch_bounds__(256, 1) k_mma_skip(const float* __restrict__ bias){
  mma_core<128, true>(g_wbhi + 4*32768, g_wblo + 4*32768, bias);
}

// ================= GATv2 + fused GraphNorm stats =================
__device__ __forceinline__ float lrelu(float v){ return v > 0.f ? v : 0.2f*v; }

__global__ void __launch_bounds__(256) k_gat(const float* __restrict__ att,
                                             const float* __restrict__ convb){
  __shared__ float s_sum[8][128];
  __shared__ float s_sq [8][128];
  int tid = threadIdx.x, wid = tid >> 5, lane = tid & 31;
  int node = blockIdx.x*8 + wid;
  int c4 = lane * 4;
  float4 o = make_float4(0.f, 0.f, 0.f, 0.f);

  if(node < NN){
    const float4 xr4 = *(const float4*)(g_xr + node*128 + c4);
    const float4 at4 = *(const float4*)(att + c4);
    int pb = g_rowptr[node], pe = g_rowptr[node+1];

    float m = -3.4e38f, ds = 0.f;
    float a0 = 0.f, a1 = 0.f, a2 = 0.f, a3 = 0.f;

    for(int p = pb; p < pe; p++){
      int s = g_csrc[p];
      uint2 raw = *(const uint2*)(g_xlh + s*128 + c4);
      float2 f0 = __half22float2(*(__half2*)&raw.x);
      float2 f1 = __half22float2(*(__half2*)&raw.y);
      float t = lrelu(f0.x + xr4.x)*at4.x + lrelu(f0.y + xr4.y)*at4.y
              + lrelu(f1.x + xr4.z)*at4.z + lrelu(f1.y + xr4.w)*at4.w;
      t += __shfl_xor_sync(0xffffffffu, t, 4);
      t += __shfl_xor_sync(0xffffffffu, t, 2);
      t += __shfl_xor_sync(0xffffffffu, t, 1);
      if(t <= m){
        float a = __expf(t - m);
        ds += a;
        a0 = fmaf(a, f0.x, a0); a1 = fmaf(a, f0.y, a1);
        a2 = fmaf(a, f1.x, a2); a3 = fmaf(a, f1.y, a3);
      } else {
        float f = __expf(m - t);
        ds = fmaf(ds, f, 1.f);
        a0 = fmaf(a0, f, f0.x); a1 = fmaf(a1, f, f0.y);
        a2 = fmaf(a2, f, f1.x); a3 = fmaf(a3, f, f1.y);
        m = t;
      }
    }
    float inv = 1.f / ds;
    const float4 bb = *(const float4*)(convb + c4);
    o.x = fmaf(a0, inv, bb.x); o.y = fmaf(a1, inv, bb.y);
    o.z = fmaf(a2, inv, bb.z); o.w = fmaf(a3, inv, bb.w);
    *(float4*)(g_h + node*128 + c4) = o;
  }

  s_sum[wid][c4]   = o.x;     s_sum[wid][c4+1] = o.y;
  s_sum[wid][c4+2] = o.z;     s_sum[wid][c4+3] = o.w;
  s_sq [wid][c4]   = o.x*o.x; s_sq [wid][c4+1] = o.y*o.y;
  s_sq [wid][c4+2] = o.z*o.z; s_sq [wid][c4+3] = o.w*o.w;
  __syncthreads();
  if(tid < 128){
    float s = 0.f, q = 0.f;
    #pragma unroll
    for(int w = 0; w < 8; w++){ s += s_sum[w][tid]; q += s_sq[w][tid]; }
    atomicAdd(&g_stats[tid], s);
    atomicAdd(&g_stats[128 + tid], q);
  }
}

// params + reset stats for next use
__global__ void k_params(const float* __restrict__ w, const float* __restrict__ b,
                         const float* __restrict__ ms){
  int c = threadIdx.x;
  if(c < HID){
    float sum = g_stats[c], sq = g_stats[128 + c];
    float mean = sum * (1.f/(float)NN);
    float m = ms[c] * mean;
    float var = sq * (1.f/(float)NN) - 2.f*m*mean + m*m;
    float sc = w[c] * rsqrtf(var + EPSV);
    g_scale[c] = sc;
    g_shift[c] = b[c] - m*sc;
    g_stats[c] = 0.f; g_stats[128 + c] = 0.f;
  }
}

// ================= final FC =================
__global__ void k_fc(const float* __restrict__ fw, const float* __restrict__ fb,
                     float* __restrict__ out){
  int warp = (blockIdx.x*blockDim.x + threadIdx.x) >> 5;
  if(warp >= NN) return;
  int lane = threadIdx.x & 31;
  float4 v = *(const float4*)(g_x + warp*128 + lane*4);
  float4 w = *(const float4*)(fw + lane*4);
  float s = v.x*w.x + v.y*w.y + v.z*w.z + v.w*w.w;
  #pragma unroll
  for(int o = 16; o > 0; o >>= 1) s += __shfl_xor_sync(0xffffffffu, s, o);
  if(lane == 0) out[warp] = s + fb[0];
}

// ================= launcher =================
extern "C" void kernel_launch(void* const* d_in, const int* in_sizes, int n_in,
                              void* d_out, int out_size){
  const float* x     = (const float*)d_in[0];
  const int*   ei    = (const int*)  d_in[1];
  const float* Wl    = (const float*)d_in[2];
  const float* Wr    = (const float*)d_in[3];
  const float* att   = (const float*)d_in[4];
  const float* convb = (const float*)d_in[5];
  const float* gnw   = (const float*)d_in[6];
  const float* gnb   = (const float*)d_in[7];
  const float* gnms  = (const float*)d_in[8];
  const float* skW   = (const float*)d_in[9];
  const float* skb   = (const float*)d_in[10];
  const float* fcW   = (const float*)d_in[11];
  const float* fcb   = (const float*)d_in[12];
  float* out = (float*)d_out;

  static int cfg_done = 0;
  if(!cfg_done){
    cudaFuncSetAttribute(k_mma_lr,   cudaFuncAttributeMaxDynamicSharedMemorySize, 196608);
    cudaFuncSetAttribute(k_mma_skip, cudaFuncAttributeMaxDynamicSharedMemorySize, 131072);
    cfg_done = 1;
  }

  k_init     <<<(NN*32 + 255)/256, 256>>>(x);
  k_count    <<<(NT    + 255)/256, 256>>>(ei);
  k_blocksum <<<SCAN_B, 256>>>();
  k_scan_bsum<<<1, 256>>>();
  k_rowptr   <<<SCAN_B, 256>>>();
  k_scatter  <<<(NT    + 255)/256, 256>>>(ei);
  k_cvt_w    <<<(4*32768 + 16384 + 255)/256, 256>>>(Wl, Wr, skW);

  const int MMA_GRID = (NN + 127)/128;       // 391
  const int GAT_GRID = (NN + 7)/8;           // 6250
  for(int l = 0; l < 4; l++){
    k_mma_lr  <<<MMA_GRID, 512, 196608>>>(l);
    k_gat     <<<GAT_GRID, 256>>>(att + l*HID, convb + l*HID);
    k_params  <<<1, 128>>>(gnw + l*HID, gnb + l*HID, gnms + l*HID);
    k_mma_skip<<<MMA_GRID, 256, 131072>>>(skb);
  }
  k_fc<<<(NN*32 + 255)/256, 256>>>(fcW, fcb, out);
}

// round 5
// speedup vs baseline: 1.7234x; 1.0943x over previous
#include <cuda_runtime.h>
#include <cuda_bf16.h>
#include <cuda_fp16.h>
#include <math.h>
#include <cstdint>

#define NN 50000
#define NE 800000
#define NT 850000          // NE + NN self loops
#define HID 128
#define EPSV 1e-5f

// ================= scratch (device globals; no allocations) =================
__device__ __align__(16) float g_x [NN*HID];
__device__ __align__(16) float g_xr[NN*HID];
__device__ __align__(16) float g_h [NN*HID];
__device__ __align__(16) __half g_xlh[NN*HID];          // xl in fp16 (gather table)
__device__ __align__(16) __nv_bfloat16 g_ahi[NN*HID];   // x split hi (layer-0 feed only)
__device__ __align__(16) __nv_bfloat16 g_alo[NN*HID];   // x split lo
// weights: 4 layers x [k=128][n=256] ([Wl|Wr]) + skip [k=128][n=128]
__device__ __align__(16) __nv_bfloat16 g_wbhi[4*32768 + 16384];
__device__ __align__(16) __nv_bfloat16 g_wblo[4*32768 + 16384];
__device__ int   g_cnt[NN];
__device__ int   g_rowptr[NN+1];
__device__ int   g_fill[NN];
__device__ int   g_csrc[NT];
__device__ int   g_bsum[256];
__device__ int   g_bpre[256];
__device__ float g_stats[256];      // [0:128) sum, [128:256) sumsq; reset by last gat block
__device__ float g_scale[HID];
__device__ float g_shift[HID];
__device__ int   g_ctr;

// ================= mma.sync helpers =================
__device__ __forceinline__ uint32_t smem_u32(const void* p){
  uint32_t a;
  asm("{ .reg .u64 t; cvta.to.shared.u64 t, %1; cvt.u32.u64 %0, t; }" : "=r"(a) : "l"(p));
  return a;
}
__device__ __forceinline__ void ldm4(uint32_t* r, uint32_t a){
  asm volatile("ldmatrix.sync.aligned.m8n8.x4.shared.b16 {%0,%1,%2,%3}, [%4];"
    : "=r"(r[0]),"=r"(r[1]),"=r"(r[2]),"=r"(r[3]) : "r"(a));
}
__device__ __forceinline__ void ldm4t(uint32_t* r, uint32_t a){
  asm volatile("ldmatrix.sync.aligned.m8n8.x4.trans.shared.b16 {%0,%1,%2,%3}, [%4];"
    : "=r"(r[0]),"=r"(r[1]),"=r"(r[2]),"=r"(r[3]) : "r"(a));
}
__device__ __forceinline__ void mma_bf16(float* c, const uint32_t* a, const uint32_t* b){
  asm volatile("mma.sync.aligned.m16n8k16.row.col.f32.bf16.bf16.f32 "
    "{%0,%1,%2,%3}, {%4,%5,%6,%7}, {%8,%9}, {%0,%1,%2,%3};"
    : "+f"(c[0]),"+f"(c[1]),"+f"(c[2]),"+f"(c[3])
    : "r"(a[0]),"r"(a[1]),"r"(a[2]),"r"(a[3]), "r"(b[0]),"r"(b[1]));
}
__device__ __forceinline__ uint32_t swA(int r, int c2){
  int u = c2 >> 4;
  u = (u & 8) | ((u ^ (r & 7)) & 7);
  return (uint32_t)(r*256 + (u << 4) + (c2 & 15));
}
template<int RS>
__device__ __forceinline__ uint32_t swB(int r, int c2){
  int u = c2 >> 4;
  u = (u & ~7) | ((u ^ (r & 7)) & 7);
  return (uint32_t)(r*RS + (u << 4) + (c2 & 15));
}

#define SM_ALO 32768
#define SM_B   65536

// generic 3-term compute: acc[MT][4][4]; A hi @0, A lo @32768, B hi @65536, B lo @65536+BB
template<int NCOLS, int NWARPS>
__device__ __forceinline__ void mma_compute(uint32_t sb, float acc[][4][4], int wid, int lane){
  constexpr int WNn = NCOLS/32;
  constexpr int WMm = NWARPS/WNn;
  constexpr int MT  = 128/(WMm*16);
  constexpr int BB  = NCOLS*256;
  const int warp_m = wid / WNn, warp_n = wid % WNn;
  const int arow = warp_m*(MT*16) + (lane & 15);
  const int ac2b = (lane >> 4) << 4;
  const int bgrp = lane >> 3;
  const int bkr  = ((bgrp & 1) << 3) + (lane & 7);
  const int bnc  = warp_n*32 + ((bgrp >> 1) << 3);

  #pragma unroll
  for(int ks = 0; ks < 8; ks++){
    uint32_t bh[4][2], bl[4][2], tmp[4];
    #pragma unroll
    for(int np = 0; np < 2; np++){
      uint32_t boff = swB<NCOLS*2>(ks*16 + bkr, (bnc + np*16)*2);
      ldm4t(tmp, sb + SM_B + boff);
      bh[np*2][0]=tmp[0]; bh[np*2][1]=tmp[1]; bh[np*2+1][0]=tmp[2]; bh[np*2+1][1]=tmp[3];
      ldm4t(tmp, sb + SM_B + BB + boff);
      bl[np*2][0]=tmp[0]; bl[np*2][1]=tmp[1]; bl[np*2+1][0]=tmp[2]; bl[np*2+1][1]=tmp[3];
    }
    uint32_t a[MT][4];
    #pragma unroll
    for(int mt = 0; mt < MT; mt++)
      ldm4(a[mt], sb + swA(arow + mt*16, ks*32 + ac2b));
    #pragma unroll
    for(int mt = 0; mt < MT; mt++)
      #pragma unroll
      for(int nt = 0; nt < 4; nt++){
        mma_bf16(acc[mt][nt], a[mt], bh[nt]);
        mma_bf16(acc[mt][nt], a[mt], bl[nt]);
      }
    #pragma unroll
    for(int mt = 0; mt < MT; mt++)
      ldm4(a[mt], sb + SM_ALO + swA(arow + mt*16, ks*32 + ac2b));
    #pragma unroll
    for(int mt = 0; mt < MT; mt++)
      #pragma unroll
      for(int nt = 0; nt < 4; nt++)
        mma_bf16(acc[mt][nt], a[mt], bh[nt]);
  }
}

template<int NCOLS, int TB>
__device__ __forceinline__ void fill_B(char* smem, int tid,
  const __nv_bfloat16* __restrict__ Bhi_g, const __nv_bfloat16* __restrict__ Blo_g){
  constexpr int BB  = NCOLS*256;
  constexpr int UPR = NCOLS/8;
  for(int ch = tid; ch < NCOLS*16; ch += TB){
    int r = ch / UPR, c2 = (ch % UPR) * 16;
    uint32_t off = swB<NCOLS*2>(r, c2);
    *(uint4*)(smem + SM_B + off)      = *(const uint4*)(Bhi_g + r*NCOLS + (c2 >> 1));
    *(uint4*)(smem + SM_B + BB + off) = *(const uint4*)(Blo_g + r*NCOLS + (c2 >> 1));
  }
}

// ================= setup =================
__global__ void k_init(const float* __restrict__ x){
  int i = blockIdx.x*blockDim.x + threadIdx.x;
  if(i < NN) g_cnt[i] = 0;
  if(i >= NN*32) return;
  float4 v = ((const float4*)x)[i];
  ((float4*)g_x)[i] = v;
  __nv_bfloat162 h0, h1, l0, l1;
  h0.x = __float2bfloat16_rn(v.x); h0.y = __float2bfloat16_rn(v.y);
  h1.x = __float2bfloat16_rn(v.z); h1.y = __float2bfloat16_rn(v.w);
  l0.x = __float2bfloat16_rn(v.x - __bfloat162float(h0.x));
  l0.y = __float2bfloat16_rn(v.y - __bfloat162float(h0.y));
  l1.x = __float2bfloat16_rn(v.z - __bfloat162float(h1.x));
  l1.y = __float2bfloat16_rn(v.w - __bfloat162float(h1.y));
  ((__nv_bfloat162*)g_ahi)[2*i] = h0; ((__nv_bfloat162*)g_ahi)[2*i+1] = h1;
  ((__nv_bfloat162*)g_alo)[2*i] = l0; ((__nv_bfloat162*)g_alo)[2*i+1] = l1;
}
__global__ void k_count(const int* __restrict__ ei){
  int i = blockIdx.x*blockDim.x + threadIdx.x;
  if(i >= NT) return;
  int d = (i < NE) ? ei[NE + i] : (i - NE);
  atomicAdd(&g_cnt[d], 1);
}
#define SCAN_B 196
__global__ void k_blocksum(){
  __shared__ int sh[256];
  int t = threadIdx.x;
  int i = blockIdx.x*256 + t;
  sh[t] = (i < NN) ? g_cnt[i] : 0; __syncthreads();
  #pragma unroll
  for(int off = 128; off > 0; off >>= 1){
    if(t < off) sh[t] += sh[t+off];
    __syncthreads();
  }
  if(t == 0) g_bsum[blockIdx.x] = sh[0];
}
__global__ void k_scan_bsum(){
  __shared__ int sh[256];
  int t = threadIdx.x;
  int v = (t < SCAN_B) ? g_bsum[t] : 0;
  sh[t] = v; __syncthreads();
  #pragma unroll
  for(int off = 1; off < 256; off <<= 1){
    int u = (t >= off) ? sh[t-off] : 0;
    __syncthreads(); sh[t] += u; __syncthreads();
  }
  if(t < SCAN_B) g_bpre[t] = sh[t] - v;
  if(t == 255) g_rowptr[NN] = sh[255];
}
__global__ void k_rowptr(){
  __shared__ int sh[256];
  int t = threadIdx.x;
  int i = blockIdx.x*256 + t;
  int v = (i < NN) ? g_cnt[i] : 0;
  sh[t] = v; __syncthreads();
  #pragma unroll
  for(int off = 1; off < 256; off <<= 1){
    int u = (t >= off) ? sh[t-off] : 0;
    __syncthreads(); sh[t] += u; __syncthreads();
  }
  if(i < NN){
    int e = sh[t] - v + g_bpre[blockIdx.x];
    g_rowptr[i] = e; g_fill[i] = e;
  }
}
__global__ void k_scatter(const int* __restrict__ ei){
  int i = blockIdx.x*blockDim.x + threadIdx.x;
  if(i >= NT) return;
  int s, d;
  if(i < NE){ s = ei[i]; d = ei[NE + i]; }
  else      { s = d = i - NE; }
  int pos = atomicAdd(&g_fill[d], 1);
  g_csrc[pos] = s;
}
__global__ void k_cvt_w(const float* __restrict__ Wl, const float* __restrict__ Wr,
                        const float* __restrict__ skW){
  int i = blockIdx.x*blockDim.x + threadIdx.x;
  if(i >= 4*32768 + 16384) return;
  float v;
  if(i < 4*32768){
    int l = i >> 15, rem = i & 32767, k = rem >> 8, n = rem & 255;
    v = (n < 128) ? Wl[l*16384 + k*128 + n] : Wr[l*16384 + k*128 + (n-128)];
  } else {
    v = skW[i - 4*32768];
  }
  __nv_bfloat16 h = __float2bfloat16_rn(v);
  g_wbhi[i] = h;
  g_wblo[i] = __float2bfloat16_rn(v - __bfloat162float(h));
}

// ================= layer-0 LR GEMM (A from g_ahi/g_alo) =================
__device__ __forceinline__ void lr_epilogue(float acc[][4][4], int bm, int wid, int lane){
  const int warp_m = wid >> 3, warp_n = wid & 7;   // NWARPS=16, WN=8 -> MT=4
  #pragma unroll
  for(int mt = 0; mt < 4; mt++){
    int r0 = bm + warp_m*64 + mt*16 + (lane >> 2);
    #pragma unroll
    for(int nt = 0; nt < 4; nt++){
      int colg = warp_n*32 + nt*8 + (lane & 3)*2;
      #pragma unroll
      for(int half = 0; half < 2; half++){
        int grow = r0 + half*8;
        if(grow >= NN) continue;
        float v0 = acc[mt][nt][half*2], v1 = acc[mt][nt][half*2+1];
        if(colg < 128)
          *(__half2*)(g_xlh + grow*128 + colg) = __floats2half2_rn(v0, v1);
        else
          *(float2*)(g_xr + grow*128 + (colg - 128)) = make_float2(v0, v1);
      }
    }
  }
}

__global__ void __launch_bounds__(512, 1) k_mma_lr0(){
  extern __shared__ __align__(16) char smem[];
  const int tid = threadIdx.x, wid = tid >> 5, lane = tid & 31;
  const int bm = blockIdx.x * 128;
  const uint32_t sb = smem_u32(smem);
  for(int ch = tid; ch < 2048; ch += 512){
    int r = ch >> 4, c2 = (ch & 15) << 4;
    int grow = bm + r;
    uint32_t off = swA(r, c2);
    uint4 vh = make_uint4(0,0,0,0), vl = vh;
    if(grow < NN){
      vh = *(const uint4*)(g_ahi + grow*128 + (c2 >> 1));
      vl = *(const uint4*)(g_alo + grow*128 + (c2 >> 1));
    }
    *(uint4*)(smem + off)          = vh;
    *(uint4*)(smem + SM_ALO + off) = vl;
  }
  fill_B<256, 512>(smem, tid, g_wbhi, g_wblo);
  __syncthreads();
  float acc[4][4][4];
  #pragma unroll
  for(int mt = 0; mt < 4; mt++)
    #pragma unroll
    for(int nt = 0; nt < 4; nt++)
      #pragma unroll
      for(int r = 0; r < 4; r++) acc[mt][nt][r] = 0.f;
  mma_compute<256, 16>(sb, acc, wid, lane);
  lr_epilogue(acc, bm, wid, lane);
}

// ================= fused skip-GEMM (+ optional next-layer LR GEMM) =================
// xnew = normelu(g_h) @ skW + skb + x  -> g_x ; splits stay in SMEM; then LR GEMM.
template<bool DO_LR>
__global__ void __launch_bounds__(512, 1) k_fused(const float* __restrict__ bias, int next_layer){
  extern __shared__ __align__(16) char smem[];
  const int tid = threadIdx.x, wid = tid >> 5, lane = tid & 31;
  const int bm = blockIdx.x * 128;
  const uint32_t sb = smem_u32(smem);

  // ---- prologue: A = split(normelu(h)), B = skW ----
  for(int ch = tid; ch < 2048; ch += 512){
    int r = ch >> 4, c2 = (ch & 15) << 4;
    int grow = bm + r;
    uint32_t off = swA(r, c2);
    int c = c2 >> 1;
    __nv_bfloat162 hh[4], ll[4];
    if(grow < NN){
      #pragma unroll
      for(int q = 0; q < 2; q++){
        float4 v  = *(const float4*)(g_h + grow*128 + c + q*4);
        float4 sc = *(const float4*)(g_scale + c + q*4);
        float4 sh = *(const float4*)(g_shift + c + q*4);
        float z0 = fmaf(v.x, sc.x, sh.x); z0 = z0 > 0.f ? z0 : (__expf(z0) - 1.f);
        float z1 = fmaf(v.y, sc.y, sh.y); z1 = z1 > 0.f ? z1 : (__expf(z1) - 1.f);
        float z2 = fmaf(v.z, sc.z, sh.z); z2 = z2 > 0.f ? z2 : (__expf(z2) - 1.f);
        float z3 = fmaf(v.w, sc.w, sh.w); z3 = z3 > 0.f ? z3 : (__expf(z3) - 1.f);
        hh[q*2].x   = __float2bfloat16_rn(z0); hh[q*2].y   = __float2bfloat16_rn(z1);
        hh[q*2+1].x = __float2bfloat16_rn(z2); hh[q*2+1].y = __float2bfloat16_rn(z3);
        ll[q*2].x   = __float2bfloat16_rn(z0 - __bfloat162float(hh[q*2].x));
        ll[q*2].y   = __float2bfloat16_rn(z1 - __bfloat162float(hh[q*2].y));
        ll[q*2+1].x = __float2bfloat16_rn(z2 - __bfloat162float(hh[q*2+1].x));
        ll[q*2+1].y = __float2bfloat16_rn(z3 - __bfloat162float(hh[q*2+1].y));
      }
    } else {
      #pragma unroll
      for(int q = 0; q < 4; q++){ hh[q].x = hh[q].y = __float2bfloat16_rn(0.f); ll[q] = hh[q]; }
    }
    *(uint4*)(smem + off)          = *(uint4*)hh;
    *(uint4*)(smem + SM_ALO + off) = *(uint4*)ll;
  }
  fill_B<128, 512>(smem, tid, g_wbhi + 4*32768, g_wblo + 4*32768);
  __syncthreads();

  // ---- skip compute: NCOLS=128, 16 warps -> MT=2 ----
  {
    float acc[2][4][4];
    #pragma unroll
    for(int mt = 0; mt < 2; mt++)
      #pragma unroll
      for(int nt = 0; nt < 4; nt++)
        #pragma unroll
        for(int r = 0; r < 4; r++) acc[mt][nt][r] = 0.f;
    mma_compute<128, 16>(sb, acc, wid, lane);
    __syncthreads();               // all reads of A/B smem done

    // ---- epilogue: x update + splits into SMEM A ----
    const int warp_m = wid >> 2, warp_n = wid & 3;
    #pragma unroll
    for(int mt = 0; mt < 2; mt++){
      int rloc0 = warp_m*32 + mt*16 + (lane >> 2);
      #pragma unroll
      for(int nt = 0; nt < 4; nt++){
        int col = warp_n*32 + nt*8 + (lane & 3)*2;
        #pragma unroll
        for(int half = 0; half < 2; half++){
          int rloc = rloc0 + half*8;
          int grow = bm + rloc;
          float v0 = acc[mt][nt][half*2], v1 = acc[mt][nt][half*2+1];
          if(grow < NN){
            float2 old = *(const float2*)(g_x + grow*128 + col);
            v0 += bias[col]   + old.x;
            v1 += bias[col+1] + old.y;
            *(float2*)(g_x + grow*128 + col) = make_float2(v0, v1);
          } else { v0 = 0.f; v1 = 0.f; }
          if(DO_LR){
            __nv_bfloat162 h, l;
            h.x = __float2bfloat16_rn(v0); h.y = __float2bfloat16_rn(v1);
            l.x = __float2bfloat16_rn(v0 - __bfloat162float(h.x));
            l.y = __float2bfloat16_rn(v1 - __bfloat162float(h.y));
            uint32_t off = swA(rloc, col*2);
            *(__nv_bfloat162*)(smem + off)          = h;
            *(__nv_bfloat162*)(smem + SM_ALO + off) = l;
          }
        }
      }
    }
  }
  if(!DO_LR) return;

  // ---- reload B with next-layer [Wl|Wr]; A already holds new-x splits ----
  fill_B<256, 512>(smem, tid, g_wbhi + next_layer*32768, g_wblo + next_layer*32768);
  __syncthreads();

  float acc[4][4][4];
  #pragma unroll
  for(int mt = 0; mt < 4; mt++)
    #pragma unroll
    for(int nt = 0; nt < 4; nt++)
      #pragma unroll
      for(int r = 0; r < 4; r++) acc[mt][nt][r] = 0.f;
  mma_compute<256, 16>(sb, acc, wid, lane);
  lr_epilogue(acc, bm, wid, lane);
}

// ================= GATv2 + fused GraphNorm stats + last-block params =================
__device__ __forceinline__ float lrelu(float v){ return v > 0.f ? v : 0.2f*v; }

__global__ void __launch_bounds__(256) k_gat(const float* __restrict__ att,
                                             const float* __restrict__ convb,
                                             const float* __restrict__ gnw,
                                             const float* __restrict__ gnb,
                                             const float* __restrict__ gnms){
  __shared__ float s_sum[8][128];
  __shared__ float s_sq [8][128];
  __shared__ int s_last;
  int tid = threadIdx.x, wid = tid >> 5, lane = tid & 31;
  int node = blockIdx.x*8 + wid;
  int c4 = lane * 4;
  float4 o = make_float4(0.f, 0.f, 0.f, 0.f);

  if(node < NN){
    const float4 xr4 = *(const float4*)(g_xr + node*128 + c4);
    const float4 at4 = *(const float4*)(att + c4);
    int pb = g_rowptr[node], pe = g_rowptr[node+1];

    float m = -3.4e38f, ds = 0.f;
    float a0 = 0.f, a1 = 0.f, a2 = 0.f, a3 = 0.f;

    for(int p = pb; p < pe; p++){
      int s = g_csrc[p];
      uint2 raw = *(const uint2*)(g_xlh + s*128 + c4);
      float2 f0 = __half22float2(*(__half2*)&raw.x);
      float2 f1 = __half22float2(*(__half2*)&raw.y);
      float t = lrelu(f0.x + xr4.x)*at4.x + lrelu(f0.y + xr4.y)*at4.y
              + lrelu(f1.x + xr4.z)*at4.z + lrelu(f1.y + xr4.w)*at4.w;
      t += __shfl_xor_sync(0xffffffffu, t, 4);
      t += __shfl_xor_sync(0xffffffffu, t, 2);
      t += __shfl_xor_sync(0xffffffffu, t, 1);
      if(t <= m){
        float a = __expf(t - m);
        ds += a;
        a0 = fmaf(a, f0.x, a0); a1 = fmaf(a, f0.y, a1);
        a2 = fmaf(a, f1.x, a2); a3 = fmaf(a, f1.y, a3);
      } else {
        float f = __expf(m - t);
        ds = fmaf(ds, f, 1.f);
        a0 = fmaf(a0, f, f0.x); a1 = fmaf(a1, f, f0.y);
        a2 = fmaf(a2, f, f1.x); a3 = fmaf(a3, f, f1.y);
        m = t;
      }
    }
    float inv = 1.f / ds;
    const float4 bb = *(const float4*)(convb + c4);
    o.x = fmaf(a0, inv, bb.x); o.y = fmaf(a1, inv, bb.y);
    o.z = fmaf(a2, inv, bb.z); o.w = fmaf(a3, inv, bb.w);
    *(float4*)(g_h + node*128 + c4) = o;
  }

  s_sum[wid][c4]   = o.x;     s_sum[wid][c4+1] = o.y;
  s_sum[wid][c4+2] = o.z;     s_sum[wid][c4+3] = o.w;
  s_sq [wid][c4]   = o.x*o.x; s_sq [wid][c4+1] = o.y*o.y;
  s_sq [wid][c4+2] = o.z*o.z; s_sq [wid][c4+3] = o.w*o.w;
  __syncthreads();
  if(tid < 128){
    float s = 0.f, q = 0.f;
    #pragma unroll
    for(int w = 0; w < 8; w++){ s += s_sum[w][tid]; q += s_sq[w][tid]; }
    atomicAdd(&g_stats[tid], s);
    atomicAdd(&g_stats[128 + tid], q);
  }
  // last CTA computes norm params
  __threadfence();
  if(tid == 0){
    int v = atomicAdd(&g_ctr, 1);
    s_last = (v == (int)gridDim.x - 1);
  }
  __syncthreads();
  if(s_last){
    if(tid < 128){
      float sum = g_stats[tid], sq = g_stats[128 + tid];
      float mean = sum * (1.f/(float)NN);
      float m = gnms[tid] * mean;
      float var = sq * (1.f/(float)NN) - 2.f*m*mean + m*m;
      float sc = gnw[tid] * rsqrtf(var + EPSV);
      g_scale[tid] = sc;
      g_shift[tid] = gnb[tid] - m*sc;
      g_stats[tid] = 0.f; g_stats[128 + tid] = 0.f;
    }
    if(tid == 0) g_ctr = 0;
  }
}

// ================= final FC =================
__global__ void k_fc(const float* __restrict__ fw, const float* __restrict__ fb,
                     float* __restrict__ out){
  int warp = (blockIdx.x*blockDim.x + threadIdx.x) >> 5;
  if(warp >= NN) return;
  int lane = threadIdx.x & 31;
  float4 v = *(const float4*)(g_x + warp*128 + lane*4);
  float4 w = *(const float4*)(fw + lane*4);
  float s = v.x*w.x + v.y*w.y + v.z*w.z + v.w*w.w;
  #pragma unroll
  for(int o = 16; o > 0; o >>= 1) s += __shfl_xor_sync(0xffffffffu, s, o);
  if(lane == 0) out[warp] = s + fb[0];
}

// ================= launcher =================
extern "C" void kernel_launch(void* const* d_in, const int* in_sizes, int n_in,
                              void* d_out, int out_size){
  const float* x     = (const float*)d_in[0];
  const int*   ei    = (const int*)  d_in[1];
  const float* Wl    = (const float*)d_in[2];
  const float* Wr    = (const float*)d_in[3];
  const float* att   = (const float*)d_in[4];
  const float* convb = (const float*)d_in[5];
  const float* gnw   = (const float*)d_in[6];
  const float* gnb   = (const float*)d_in[7];
  const float* gnms  = (const float*)d_in[8];
  const float* skW   = (const float*)d_in[9];
  const float* skb   = (const float*)d_in[10];
  const float* fcW   = (const float*)d_in[11];
  const float* fcb   = (const float*)d_in[12];
  float* out = (float*)d_out;

  static int cfg_done = 0;
  if(!cfg_done){
    cudaFuncSetAttribute(k_mma_lr0,      cudaFuncAttributeMaxDynamicSharedMemorySize, 196608);
    cudaFuncSetAttribute(k_fused<true>,  cudaFuncAttributeMaxDynamicSharedMemorySize, 196608);
    cudaFuncSetAttribute(k_fused<false>, cudaFuncAttributeMaxDynamicSharedMemorySize, 196608);
    cfg_done = 1;
  }

  k_init     <<<(NN*32 + 255)/256, 256>>>(x);
  k_count    <<<(NT    + 255)/256, 256>>>(ei);
  k_blocksum <<<SCAN_B, 256>>>();
  k_scan_bsum<<<1, 256>>>();
  k_rowptr   <<<SCAN_B, 256>>>();
  k_scatter  <<<(NT    + 255)/256, 256>>>(ei);
  k_cvt_w    <<<(4*32768 + 16384 + 255)/256, 256>>>(Wl, Wr, skW);

  const int MMA_GRID = (NN + 127)/128;       // 391
  const int GAT_GRID = (NN + 7)/8;           // 6250
  k_mma_lr0<<<MMA_GRID, 512, 196608>>>();
  for(int l = 0; l < 4; l++){
    k_gat<<<GAT_GRID, 256>>>(att + l*HID, convb + l*HID,
                             gnw + l*HID, gnb + l*HID, gnms + l*HID);
    if(l < 3) k_fused<true> <<<MMA_GRID, 512, 196608>>>(skb, l + 1);
    else      k_fused<false><<<MMA_GRID, 512, 196608>>>(skb, 0);
  }
  k_fc<<<(NN*32 + 255)/256, 256>>>(fcW, fcb, out);
}

// round 6
// speedup vs baseline: 2.0567x; 1.1934x over previous
#include <cuda_runtime.h>
#include <cuda_bf16.h>
#include <cuda_fp16.h>
#include <math.h>
#include <cstdint>

#define NN 50000
#define NE 800000
#define NT 850000          // NE + NN self loops
#define HID 128
#define EPSV 1e-5f

// ================= scratch (device globals; no allocations) =================
__device__ __align__(16) float g_x [NN*HID];
__device__ __align__(16) float g_xr[NN*HID];
__device__ __align__(16) float g_h [NN*HID];
__device__ __align__(16) __half g_xlh[NN*HID];   // xl fp16 gather table
__device__ __align__(16) __half g_ahi[NN*HID];   // x split hi (fp16) - layer0 feed
__device__ __align__(16) __half g_alo[NN*HID];   // x split lo (fp16)
// weights fp16: 4 layers x [k=128][n=256] ([Wl|Wr]) + skip [k=128][n=128]
__device__ __align__(16) __half g_wh[4*32768 + 16384];
__device__ int   g_cnt[NN];
__device__ int   g_rowptr[NN+1];
__device__ int   g_fill[NN];
__device__ int   g_csrc[NT];
__device__ int   g_bsum[256];
__device__ int   g_bpre[256];
__device__ float g_stats[256];      // sum / sumsq; reset by last gat block
__device__ float g_scale[HID];
__device__ float g_shift[HID];
__device__ int   g_ctr;

// ================= mma.sync helpers =================
__device__ __forceinline__ uint32_t smem_u32(const void* p){
  uint32_t a;
  asm("{ .reg .u64 t; cvta.to.shared.u64 t, %1; cvt.u32.u64 %0, t; }" : "=r"(a) : "l"(p));
  return a;
}
__device__ __forceinline__ void ldm4(uint32_t* r, uint32_t a){
  asm volatile("ldmatrix.sync.aligned.m8n8.x4.shared.b16 {%0,%1,%2,%3}, [%4];"
    : "=r"(r[0]),"=r"(r[1]),"=r"(r[2]),"=r"(r[3]) : "r"(a));
}
__device__ __forceinline__ void ldm4t(uint32_t* r, uint32_t a){
  asm volatile("ldmatrix.sync.aligned.m8n8.x4.trans.shared.b16 {%0,%1,%2,%3}, [%4];"
    : "=r"(r[0]),"=r"(r[1]),"=r"(r[2]),"=r"(r[3]) : "r"(a));
}
__device__ __forceinline__ void mma_f16(float* c, const uint32_t* a, const uint32_t* b){
  asm volatile("mma.sync.aligned.m16n8k16.row.col.f32.f16.f16.f32 "
    "{%0,%1,%2,%3}, {%4,%5,%6,%7}, {%8,%9}, {%0,%1,%2,%3};"
    : "+f"(c[0]),"+f"(c[1]),"+f"(c[2]),"+f"(c[3])
    : "r"(a[0]),"r"(a[1]),"r"(a[2]),"r"(a[3]), "r"(b[0]),"r"(b[1]));
}
__device__ __forceinline__ uint32_t swA(int r, int c2){
  int u = c2 >> 4;
  u = (u & 8) | ((u ^ (r & 7)) & 7);
  return (uint32_t)(r*256 + (u << 4) + (c2 & 15));
}
template<int RS>
__device__ __forceinline__ uint32_t swB(int r, int c2){
  int u = c2 >> 4;
  u = (u & ~7) | ((u ^ (r & 7)) & 7);
  return (uint32_t)(r*RS + (u << 4) + (c2 & 15));
}

#define SM_ALO 32768
#define SM_B   65536

// 2-term compute: D = Ahi@B + Alo@B.  A hi @0, A lo @32768, B @65536.
template<int NCOLS, int NWARPS>
__device__ __forceinline__ void mma_compute(uint32_t sb, float acc[][4][4], int wid, int lane){
  constexpr int WNn = NCOLS/32;
  constexpr int WMm = NWARPS/WNn;
  constexpr int MT  = 128/(WMm*16);
  const int warp_m = wid / WNn, warp_n = wid % WNn;
  const int arow = warp_m*(MT*16) + (lane & 15);
  const int ac2b = (lane >> 4) << 4;
  const int bgrp = lane >> 3;
  const int bkr  = ((bgrp & 1) << 3) + (lane & 7);
  const int bnc  = warp_n*32 + ((bgrp >> 1) << 3);

  #pragma unroll
  for(int ks = 0; ks < 8; ks++){
    uint32_t bf[4][2], tmp[4];
    #pragma unroll
    for(int np = 0; np < 2; np++){
      uint32_t boff = swB<NCOLS*2>(ks*16 + bkr, (bnc + np*16)*2);
      ldm4t(tmp, sb + SM_B + boff);
      bf[np*2][0]=tmp[0]; bf[np*2][1]=tmp[1]; bf[np*2+1][0]=tmp[2]; bf[np*2+1][1]=tmp[3];
    }
    uint32_t a[MT][4];
    #pragma unroll
    for(int mt = 0; mt < MT; mt++)
      ldm4(a[mt], sb + swA(arow + mt*16, ks*32 + ac2b));
    #pragma unroll
    for(int mt = 0; mt < MT; mt++)
      #pragma unroll
      for(int nt = 0; nt < 4; nt++)
        mma_f16(acc[mt][nt], a[mt], bf[nt]);
    #pragma unroll
    for(int mt = 0; mt < MT; mt++)
      ldm4(a[mt], sb + SM_ALO + swA(arow + mt*16, ks*32 + ac2b));
    #pragma unroll
    for(int mt = 0; mt < MT; mt++)
      #pragma unroll
      for(int nt = 0; nt < 4; nt++)
        mma_f16(acc[mt][nt], a[mt], bf[nt]);
  }
}

template<int NCOLS, int TB>
__device__ __forceinline__ void fill_B(char* smem, int tid, const __half* __restrict__ Wg){
  constexpr int UPR = NCOLS/8;
  for(int ch = tid; ch < NCOLS*16; ch += TB){
    int r = ch / UPR, c2 = (ch % UPR) * 16;
    uint32_t off = swB<NCOLS*2>(r, c2);
    *(uint4*)(smem + SM_B + off) = *(const uint4*)(Wg + r*NCOLS + (c2 >> 1));
  }
}

// ================= setup =================
__global__ void k_init(const float* __restrict__ x){
  int i = blockIdx.x*blockDim.x + threadIdx.x;
  if(i < NN) g_cnt[i] = 0;
  if(i >= NN*32) return;
  float4 v = ((const float4*)x)[i];
  ((float4*)g_x)[i] = v;
  __half2 h0, h1, l0, l1;
  h0.x = __float2half_rn(v.x); h0.y = __float2half_rn(v.y);
  h1.x = __float2half_rn(v.z); h1.y = __float2half_rn(v.w);
  l0.x = __float2half_rn(v.x - __half2float(h0.x));
  l0.y = __float2half_rn(v.y - __half2float(h0.y));
  l1.x = __float2half_rn(v.z - __half2float(h1.x));
  l1.y = __float2half_rn(v.w - __half2float(h1.y));
  ((__half2*)g_ahi)[2*i] = h0; ((__half2*)g_ahi)[2*i+1] = h1;
  ((__half2*)g_alo)[2*i] = l0; ((__half2*)g_alo)[2*i+1] = l1;
}
__global__ void k_count(const int* __restrict__ ei){
  int i = blockIdx.x*blockDim.x + threadIdx.x;
  if(i >= NT) return;
  int d = (i < NE) ? ei[NE + i] : (i - NE);
  atomicAdd(&g_cnt[d], 1);
}
#define SCAN_B 196
__global__ void k_blocksum(){
  __shared__ int sh[256];
  int t = threadIdx.x;
  int i = blockIdx.x*256 + t;
  sh[t] = (i < NN) ? g_cnt[i] : 0; __syncthreads();
  #pragma unroll
  for(int off = 128; off > 0; off >>= 1){
    if(t < off) sh[t] += sh[t+off];
    __syncthreads();
  }
  if(t == 0) g_bsum[blockIdx.x] = sh[0];
}
__global__ void k_scan_bsum(){
  __shared__ int sh[256];
  int t = threadIdx.x;
  int v = (t < SCAN_B) ? g_bsum[t] : 0;
  sh[t] = v; __syncthreads();
  #pragma unroll
  for(int off = 1; off < 256; off <<= 1){
    int u = (t >= off) ? sh[t-off] : 0;
    __syncthreads(); sh[t] += u; __syncthreads();
  }
  if(t < SCAN_B) g_bpre[t] = sh[t] - v;
  if(t == 255) g_rowptr[NN] = sh[255];
}
__global__ void k_rowptr(){
  __shared__ int sh[256];
  int t = threadIdx.x;
  int i = blockIdx.x*256 + t;
  int v = (i < NN) ? g_cnt[i] : 0;
  sh[t] = v; __syncthreads();
  #pragma unroll
  for(int off = 1; off < 256; off <<= 1){
    int u = (t >= off) ? sh[t-off] : 0;
    __syncthreads(); sh[t] += u; __syncthreads();
  }
  if(i < NN){
    int e = sh[t] - v + g_bpre[blockIdx.x];
    g_rowptr[i] = e; g_fill[i] = e;
  }
}
__global__ void k_scatter(const int* __restrict__ ei){
  int i = blockIdx.x*blockDim.x + threadIdx.x;
  if(i >= NT) return;
  int s, d;
  if(i < NE){ s = ei[i]; d = ei[NE + i]; }
  else      { s = d = i - NE; }
  int pos = atomicAdd(&g_fill[d], 1);
  g_csrc[pos] = s;
}
__global__ void k_cvt_w(const float* __restrict__ Wl, const float* __restrict__ Wr,
                        const float* __restrict__ skW){
  int i = blockIdx.x*blockDim.x + threadIdx.x;
  if(i >= 4*32768 + 16384) return;
  float v;
  if(i < 4*32768){
    int l = i >> 15, rem = i & 32767, k = rem >> 8, n = rem & 255;
    v = (n < 128) ? Wl[l*16384 + k*128 + n] : Wr[l*16384 + k*128 + (n-128)];
  } else {
    v = skW[i - 4*32768];
  }
  g_wh[i] = __float2half_rn(v);
}

// ================= LR epilogue (shared by lr0 and fused) =================
__device__ __forceinline__ void lr_epilogue(float acc[][4][4], int bm, int wid, int lane){
  const int warp_m = wid >> 3, warp_n = wid & 7;   // 16 warps, WN=8 -> MT=4
  #pragma unroll
  for(int mt = 0; mt < 4; mt++){
    int r0 = bm + warp_m*64 + mt*16 + (lane >> 2);
    #pragma unroll
    for(int nt = 0; nt < 4; nt++){
      int colg = warp_n*32 + nt*8 + (lane & 3)*2;
      #pragma unroll
      for(int half = 0; half < 2; half++){
        int grow = r0 + half*8;
        if(grow >= NN) continue;
        float v0 = acc[mt][nt][half*2], v1 = acc[mt][nt][half*2+1];
        if(colg < 128)
          *(__half2*)(g_xlh + grow*128 + colg) = __floats2half2_rn(v0, v1);
        else
          *(float2*)(g_xr + grow*128 + (colg - 128)) = make_float2(v0, v1);
      }
    }
  }
}

__global__ void __launch_bounds__(512, 1) k_mma_lr0(){
  extern __shared__ __align__(16) char smem[];
  const int tid = threadIdx.x, wid = tid >> 5, lane = tid & 31;
  const int bm = blockIdx.x * 128;
  const uint32_t sb = smem_u32(smem);
  for(int ch = tid; ch < 2048; ch += 512){
    int r = ch >> 4, c2 = (ch & 15) << 4;
    int grow = bm + r;
    uint32_t off = swA(r, c2);
    uint4 vh = make_uint4(0,0,0,0), vl = vh;
    if(grow < NN){
      vh = *(const uint4*)(g_ahi + grow*128 + (c2 >> 1));
      vl = *(const uint4*)(g_alo + grow*128 + (c2 >> 1));
    }
    *(uint4*)(smem + off)          = vh;
    *(uint4*)(smem + SM_ALO + off) = vl;
  }
  fill_B<256, 512>(smem, tid, g_wh);
  __syncthreads();
  float acc[4][4][4];
  #pragma unroll
  for(int mt = 0; mt < 4; mt++)
    #pragma unroll
    for(int nt = 0; nt < 4; nt++)
      #pragma unroll
      for(int r = 0; r < 4; r++) acc[mt][nt][r] = 0.f;
  mma_compute<256, 16>(sb, acc, wid, lane);
  lr_epilogue(acc, bm, wid, lane);
}

// ================= fused skip-GEMM (+ next-layer LR GEMM) =================
template<bool DO_LR>
__global__ void __launch_bounds__(512, 1) k_fused(const float* __restrict__ bias, int next_layer){
  extern __shared__ __align__(16) char smem[];
  const int tid = threadIdx.x, wid = tid >> 5, lane = tid & 31;
  const int bm = blockIdx.x * 128;
  const uint32_t sb = smem_u32(smem);

  // ---- prologue: A = fp16split(normelu(h)), B = skW ----
  for(int ch = tid; ch < 2048; ch += 512){
    int r = ch >> 4, c2 = (ch & 15) << 4;
    int grow = bm + r;
    uint32_t off = swA(r, c2);
    int c = c2 >> 1;
    __half2 hh[4], ll[4];
    if(grow < NN){
      #pragma unroll
      for(int q = 0; q < 2; q++){
        float4 v  = *(const float4*)(g_h + grow*128 + c + q*4);
        float4 sc = *(const float4*)(g_scale + c + q*4);
        float4 sh = *(const float4*)(g_shift + c + q*4);
        float z0 = fmaf(v.x, sc.x, sh.x); z0 = z0 > 0.f ? z0 : (__expf(z0) - 1.f);
        float z1 = fmaf(v.y, sc.y, sh.y); z1 = z1 > 0.f ? z1 : (__expf(z1) - 1.f);
        float z2 = fmaf(v.z, sc.z, sh.z); z2 = z2 > 0.f ? z2 : (__expf(z2) - 1.f);
        float z3 = fmaf(v.w, sc.w, sh.w); z3 = z3 > 0.f ? z3 : (__expf(z3) - 1.f);
        hh[q*2].x   = __float2half_rn(z0); hh[q*2].y   = __float2half_rn(z1);
        hh[q*2+1].x = __float2half_rn(z2); hh[q*2+1].y = __float2half_rn(z3);
        ll[q*2].x   = __float2half_rn(z0 - __half2float(hh[q*2].x));
        ll[q*2].y   = __float2half_rn(z1 - __half2float(hh[q*2].y));
        ll[q*2+1].x = __float2half_rn(z2 - __half2float(hh[q*2+1].x));
        ll[q*2+1].y = __float2half_rn(z3 - __half2float(hh[q*2+1].y));
      }
    } else {
      #pragma unroll
      for(int q = 0; q < 4; q++){ hh[q].x = hh[q].y = __float2half_rn(0.f); ll[q] = hh[q]; }
    }
    *(uint4*)(smem + off)          = *(uint4*)hh;
    *(uint4*)(smem + SM_ALO + off) = *(uint4*)ll;
  }
  fill_B<128, 512>(smem, tid, g_wh + 4*32768);
  __syncthreads();

  // ---- skip compute: NCOLS=128, 16 warps -> MT=2 ----
  {
    float acc[2][4][4];
    #pragma unroll
    for(int mt = 0; mt < 2; mt++)
      #pragma unroll
      for(int nt = 0; nt < 4; nt++)
        #pragma unroll
        for(int r = 0; r < 4; r++) acc[mt][nt][r] = 0.f;
    mma_compute<128, 16>(sb, acc, wid, lane);
    __syncthreads();

    // ---- epilogue: x update; new splits straight into SMEM A ----
    const int warp_m = wid >> 2, warp_n = wid & 3;
    #pragma unroll
    for(int mt = 0; mt < 2; mt++){
      int rloc0 = warp_m*32 + mt*16 + (lane >> 2);
      #pragma unroll
      for(int nt = 0; nt < 4; nt++){
        int col = warp_n*32 + nt*8 + (lane & 3)*2;
        #pragma unroll
        for(int half = 0; half < 2; half++){
          int rloc = rloc0 + half*8;
          int grow = bm + rloc;
          float v0 = acc[mt][nt][half*2], v1 = acc[mt][nt][half*2+1];
          if(grow < NN){
            float2 old = *(const float2*)(g_x + grow*128 + col);
            v0 += bias[col]   + old.x;
            v1 += bias[col+1] + old.y;
            *(float2*)(g_x + grow*128 + col) = make_float2(v0, v1);
          } else { v0 = 0.f; v1 = 0.f; }
          if(DO_LR){
            __half2 h, l;
            h.x = __float2half_rn(v0); h.y = __float2half_rn(v1);
            l.x = __float2half_rn(v0 - __half2float(h.x));
            l.y = __float2half_rn(v1 - __half2float(h.y));
            uint32_t off = swA(rloc, col*2);
            *(__half2*)(smem + off)          = h;
            *(__half2*)(smem + SM_ALO + off) = l;
          }
        }
      }
    }
  }
  if(!DO_LR) return;

  fill_B<256, 512>(smem, tid, g_wh + next_layer*32768);
  __syncthreads();

  float acc[4][4][4];
  #pragma unroll
  for(int mt = 0; mt < 4; mt++)
    #pragma unroll
    for(int nt = 0; nt < 4; nt++)
      #pragma unroll
      for(int r = 0; r < 4; r++) acc[mt][nt][r] = 0.f;
  mma_compute<256, 16>(sb, acc, wid, lane);
  lr_epilogue(acc, bm, wid, lane);
}

// ================= GATv2 + fused GraphNorm stats + last-block params =================
__device__ __forceinline__ float lrelu(float v){ return v > 0.f ? v : 0.2f*v; }

__global__ void __launch_bounds__(256) k_gat(const float* __restrict__ att,
                                             const float* __restrict__ convb,
                                             const float* __restrict__ gnw,
                                             const float* __restrict__ gnb,
                                             const float* __restrict__ gnms){
  __shared__ float s_sum[8][128];
  __shared__ float s_sq [8][128];
  __shared__ int s_last;
  int tid = threadIdx.x, wid = tid >> 5, lane = tid & 31;
  int node = blockIdx.x*8 + wid;
  int c4 = lane * 4;
  float4 o = make_float4(0.f, 0.f, 0.f, 0.f);

  if(node < NN){
    const float4 xr4 = *(const float4*)(g_xr + node*128 + c4);
    const float4 at4 = *(const float4*)(att + c4);
    int pb = g_rowptr[node], pe = g_rowptr[node+1];

    float m = -3.4e38f, ds = 0.f;
    float a0 = 0.f, a1 = 0.f, a2 = 0.f, a3 = 0.f;

    if(pb < pe){
      int sA = g_csrc[pb];
      uint2 rawN = *(const uint2*)(g_xlh + sA*128 + c4);
      int sB = (pb+1 < pe) ? g_csrc[pb+1] : 0;
      for(int p = pb; p < pe; p++){
        uint2 raw = rawN;
        if(p+1 < pe){
          rawN = *(const uint2*)(g_xlh + sB*128 + c4);
          if(p+2 < pe) sB = g_csrc[p+2];
        }
        float2 f0 = __half22float2(*(__half2*)&raw.x);
        float2 f1 = __half22float2(*(__half2*)&raw.y);
        float t = lrelu(f0.x + xr4.x)*at4.x + lrelu(f0.y + xr4.y)*at4.y
                + lrelu(f1.x + xr4.z)*at4.z + lrelu(f1.y + xr4.w)*at4.w;
        t += __shfl_xor_sync(0xffffffffu, t, 4);
        t += __shfl_xor_sync(0xffffffffu, t, 2);
        t += __shfl_xor_sync(0xffffffffu, t, 1);
        if(t <= m){
          float a = __expf(t - m);
          ds += a;
          a0 = fmaf(a, f0.x, a0); a1 = fmaf(a, f0.y, a1);
          a2 = fmaf(a, f1.x, a2); a3 = fmaf(a, f1.y, a3);
        } else {
          float f = __expf(m - t);
          ds = fmaf(ds, f, 1.f);
          a0 = fmaf(a0, f, f0.x); a1 = fmaf(a1, f, f0.y);
          a2 = fmaf(a2, f, f1.x); a3 = fmaf(a3, f, f1.y);
          m = t;
        }
      }
    }
    float inv = 1.f / ds;
    const float4 bb = *(const float4*)(convb + c4);
    o.x = fmaf(a0, inv, bb.x); o.y = fmaf(a1, inv, bb.y);
    o.z = fmaf(a2, inv, bb.z); o.w = fmaf(a3, inv, bb.w);
    *(float4*)(g_h + node*128 + c4) = o;
  }

  s_sum[wid][c4]   = o.x;     s_sum[wid][c4+1] = o.y;
  s_sum[wid][c4+2] = o.z;     s_sum[wid][c4+3] = o.w;
  s_sq [wid][c4]   = o.x*o.x; s_sq [wid][c4+1] = o.y*o.y;
  s_sq [wid][c4+2] = o.z*o.z; s_sq [wid][c4+3] = o.w*o.w;
  __syncthreads();
  if(tid < 128){
    float s = 0.f, q = 0.f;
    #pragma unroll
    for(int w = 0; w < 8; w++){ s += s_sum[w][tid]; q += s_sq[w][tid]; }
    atomicAdd(&g_stats[tid], s);
    atomicAdd(&g_stats[128 + tid], q);
  }
  __threadfence();
  if(tid == 0){
    int v = atomicAdd(&g_ctr, 1);
    s_last = (v == (int)gridDim.x - 1);
  }
  __syncthreads();
  if(s_last){
    if(tid < 128){
      float sum = g_stats[tid], sq = g_stats[128 + tid];
      float mean = sum * (1.f/(float)NN);
      float m = gnms[tid] * mean;
      float var = sq * (1.f/(float)NN) - 2.f*m*mean + m*m;
      float sc = gnw[tid] * rsqrtf(var + EPSV);
      g_scale[tid] = sc;
      g_shift[tid] = gnb[tid] - m*sc;
      g_stats[tid] = 0.f; g_stats[128 + tid] = 0.f;
    }
    if(tid == 0) g_ctr = 0;
  }
}

// ================= final FC =================
__global__ void k_fc(const float* __restrict__ fw, const float* __restrict__ fb,
                     float* __restrict__ out){
  int warp = (blockIdx.x*blockDim.x + threadIdx.x) >> 5;
  if(warp >= NN) return;
  int lane = threadIdx.x & 31;
  float4 v = *(const float4*)(g_x + warp*128 + lane*4);
  float4 w = *(const float4*)(fw + lane*4);
  float s = v.x*w.x + v.y*w.y + v.z*w.z + v.w*w.w;
  #pragma unroll
  for(int o = 16; o > 0; o >>= 1) s += __shfl_xor_sync(0xffffffffu, s, o);
  if(lane == 0) out[warp] = s + fb[0];
}

// ================= launcher =================
extern "C" void kernel_launch(void* const* d_in, const int* in_sizes, int n_in,
                              void* d_out, int out_size){
  const float* x     = (const float*)d_in[0];
  const int*   ei    = (const int*)  d_in[1];
  const float* Wl    = (const float*)d_in[2];
  const float* Wr    = (const float*)d_in[3];
  const float* att   = (const float*)d_in[4];
  const float* convb = (const float*)d_in[5];
  const float* gnw   = (const float*)d_in[6];
  const float* gnb   = (const float*)d_in[7];
  const float* gnms  = (const float*)d_in[8];
  const float* skW   = (const float*)d_in[9];
  const float* skb   = (const float*)d_in[10];
  const float* fcW   = (const float*)d_in[11];
  const float* fcb   = (const float*)d_in[12];
  float* out = (float*)d_out;

  static int cfg_done = 0;
  if(!cfg_done){
    cudaFuncSetAttribute(k_mma_lr0,      cudaFuncAttributeMaxDynamicSharedMemorySize, 131072);
    cudaFuncSetAttribute(k_fused<true>,  cudaFuncAttributeMaxDynamicSharedMemorySize, 131072);
    cudaFuncSetAttribute(k_fused<false>, cudaFuncAttributeMaxDynamicSharedMemorySize, 131072);
    cfg_done = 1;
  }

  k_init     <<<(NN*32 + 255)/256, 256>>>(x);
  k_count    <<<(NT    + 255)/256, 256>>>(ei);
  k_blocksum <<<SCAN_B, 256>>>();
  k_scan_bsum<<<1, 256>>>();
  k_rowptr   <<<SCAN_B, 256>>>();
  k_scatter  <<<(NT    + 255)/256, 256>>>(ei);
  k_cvt_w    <<<(4*32768 + 16384 + 255)/256, 256>>>(Wl, Wr, skW);

  const int MMA_GRID = (NN + 127)/128;       // 391
  const int GAT_GRID = (NN + 7)/8;           // 6250
  k_mma_lr0<<<MMA_GRID, 512, 131072>>>();
  for(int l = 0; l < 4; l++){
    k_gat<<<GAT_GRID, 256>>>(att + l*HID, convb + l*HID,
                             gnw + l*HID, gnb + l*HID, gnms + l*HID);
    if(l < 3) k_fused<true> <<<MMA_GRID, 512, 131072>>>(skb, l + 1);
    else      k_fused<false><<<MMA_GRID, 512, 131072>>>(skb, 0);
  }
  k_fc<<<(NN*32 + 255)/256, 256>>>(fcW, fcb, out);
}